// round 7
// baseline (speedup 1.0000x reference)
#include <cuda_runtime.h>

typedef unsigned long long ull;

#define N_ 128
#define L_ 160
#define E_ 512
#define HE_ 512
#define HD_ 1024
#define T_ 128
#define LN_ (L_*N_)
#define G4E_ 2048
#define NB_ 128u

// ---------------- scratch (device globals) ----------------
__device__ __align__(16) float g_xs[LN_*E_];
__device__ __align__(16) float g_G[2][(size_t)LN_*G4E_];
__device__ __align__(16) float g_h1[(size_t)LN_*2*HE_];
__device__ __align__(16) float g_enc[(size_t)LN_*2*HE_];
__device__ __align__(16) float g_eh[2][2][N_*HE_];   // [phase][dir]
__device__ __align__(16) float g_ec[2][N_*HE_];      // [dir]
__device__ __align__(16) float g_dh[2][N_*HD_];
__device__ __align__(16) float g_dc[N_*HD_];
__device__ int   g_amax[N_];
__device__ float g_lterm[L_*N_];

__device__ unsigned g_bcnt = 0;
__device__ volatile unsigned g_bgen = 0;

__device__ __forceinline__ void fma2(ull& d, ull a, ull b){
    asm("fma.rn.f32x2 %0, %1, %2, %0;" : "+l"(d) : "l"(a), "l"(b));
}
__device__ __forceinline__ float2 unpack2(ull v){
    float2 r; asm("mov.b64 {%0, %1}, %2;" : "=f"(r.x), "=f"(r.y) : "l"(v)); return r;
}
__device__ __forceinline__ float sigf(float x){ return 1.f/(1.f+expf(-x)); }

__device__ __forceinline__ void gridbar(){
    __syncthreads();
    if (threadIdx.x == 0) {
        unsigned g = g_bgen;
        __threadfence();
        if (atomicAdd(&g_bcnt, 1u) == NB_ - 1u) {
            atomicExch(&g_bcnt, 0u);
            __threadfence();
            g_bgen = g + 1u;
        } else {
            while (g_bgen == g) { }
        }
        __threadfence();
    }
    __syncthreads();
}

// ---------------- embedding ----------------
__global__ void k_embed(const int* __restrict__ ids, const float* __restrict__ embed)
{
    int i = blockIdx.x*blockDim.x + threadIdx.x;
    const int tot = LN_*E_/4;
    if (i >= tot) return;
    int e4 = i % (E_/4);
    int ln = i / (E_/4);
    int l = ln / N_, n = ln % N_;
    int id = ids[n*L_ + l];
    reinterpret_cast<float4*>(g_xs)[i] =
        reinterpret_cast<const float4*>(embed + (size_t)id*E_)[e4];
}

// ---------------- big input GEMM: f32x2, conflict-free B, smem double-buffered ----------------
// 128x128 tile, 256 threads, thread tile 8 rows x (4 + 4) cols (stride-4 groups at c4 and 64+c4).
__global__ __launch_bounds__(256) void k_gemm_bias(int asel, const float* __restrict__ Ball,
                                                   const float* __restrict__ biasall, int K)
{
    const float* A = asel ? g_h1 : g_xs;
    int z = blockIdx.z;
    const float* B = Ball + (size_t)z * G4E_ * K;
    const float* bias = biasall + z * G4E_;
    float* C = g_G[z];
    int m0 = blockIdx.y * 128, n0 = blockIdx.x * 128;
    __shared__ float2 As2[2][8][132];   // duplicated {a,a} pairs
    __shared__ float  Bs[2][8][132];
    int tid = threadIdx.x;
    int lr = tid >> 1, lk = (tid & 1) * 4;
    int ry = (tid >> 4) * 8;            // pair index into As2 row
    int c4 = (tid & 15) * 4;            // first col group; second at 64+c4
    ull acc[8][4];
    #pragma unroll
    for (int i = 0; i < 8; i++)
        #pragma unroll
        for (int j = 0; j < 4; j++) acc[i][j] = 0ull;
    const float* Arow = A + (size_t)(m0+lr)*K + lk;
    const float* Brow = B + (size_t)(n0+lr)*K + lk;
    float4 av = *(const float4*)(Arow);
    float4 bv = *(const float4*)(Brow);
    As2[0][lk+0][lr]=make_float2(av.x,av.x); As2[0][lk+1][lr]=make_float2(av.y,av.y);
    As2[0][lk+2][lr]=make_float2(av.z,av.z); As2[0][lk+3][lr]=make_float2(av.w,av.w);
    Bs[0][lk+0][lr]=bv.x; Bs[0][lk+1][lr]=bv.y; Bs[0][lk+2][lr]=bv.z; Bs[0][lk+3][lr]=bv.w;
    __syncthreads();
    int buf = 0;
    #pragma unroll 1
    for (int kc = 0; kc < K; kc += 8) {
        if (kc + 8 < K) {
            av = *(const float4*)(Arow + kc + 8);
            bv = *(const float4*)(Brow + kc + 8);
        }
        #pragma unroll
        for (int kk = 0; kk < 8; kk++) {
            ulonglong2 a01 = *(const ulonglong2*)&As2[buf][kk][ry+0];
            ulonglong2 a23 = *(const ulonglong2*)&As2[buf][kk][ry+2];
            ulonglong2 a45 = *(const ulonglong2*)&As2[buf][kk][ry+4];
            ulonglong2 a67 = *(const ulonglong2*)&As2[buf][kk][ry+6];
            ulonglong2 b01 = *(const ulonglong2*)&Bs[buf][kk][c4];        // cols c4..c4+3
            ulonglong2 b23 = *(const ulonglong2*)&Bs[buf][kk][64+c4];     // cols 64+c4..+3
            ull a[8] = {a01.x,a01.y,a23.x,a23.y,a45.x,a45.y,a67.x,a67.y};
            #pragma unroll
            for (int i = 0; i < 8; i++) {
                fma2(acc[i][0], a[i], b01.x);
                fma2(acc[i][1], a[i], b01.y);
                fma2(acc[i][2], a[i], b23.x);
                fma2(acc[i][3], a[i], b23.y);
            }
        }
        if (kc + 8 < K) {
            int nb = buf ^ 1;
            As2[nb][lk+0][lr]=make_float2(av.x,av.x); As2[nb][lk+1][lr]=make_float2(av.y,av.y);
            As2[nb][lk+2][lr]=make_float2(av.z,av.z); As2[nb][lk+3][lr]=make_float2(av.w,av.w);
            Bs[nb][lk+0][lr]=bv.x; Bs[nb][lk+1][lr]=bv.y; Bs[nb][lk+2][lr]=bv.z; Bs[nb][lk+3][lr]=bv.w;
            __syncthreads();
            buf = nb;
        }
    }
    #pragma unroll
    for (int i = 0; i < 8; i++) {
        float* Cp = C + (size_t)(m0+ry+i)*G4E_ + n0;
        float2 v0 = unpack2(acc[i][0]);
        float2 v1 = unpack2(acc[i][1]);
        float2 v2 = unpack2(acc[i][2]);
        float2 v3 = unpack2(acc[i][3]);
        Cp[c4+0]    = v0.x + bias[n0+c4+0];
        Cp[c4+1]    = v0.y + bias[n0+c4+1];
        Cp[c4+2]    = v1.x + bias[n0+c4+2];
        Cp[c4+3]    = v1.y + bias[n0+c4+3];
        Cp[64+c4+0] = v2.x + bias[n0+64+c4+0];
        Cp[64+c4+1] = v2.y + bias[n0+64+c4+1];
        Cp[64+c4+2] = v3.x + bias[n0+64+c4+2];
        Cp[64+c4+3] = v3.y + bias[n0+64+c4+3];
    }
}

// ================= persistent encoder layer (R5 version) =================
__global__ __launch_bounds__(256) void k_encP(int layer, const float* __restrict__ whh_all)
{
    extern __shared__ float sm[];
    float* Bs = sm;                        // [512][34]
    float* As = sm + 512*34;               // [2][16][132]
    float* gs = As + 2*16*132;             // [128][36]

    const int b  = blockIdx.x;
    const int d  = b >> 6;
    const int u0 = (b & 63) * 8;
    const int tid = threadIdx.x;
    const int t_c = tid & 15, t_r = tid >> 4;
    const int lrow = tid >> 1, lk0 = (tid & 1) * 8;

    {
        const float* wb = whh_all + (size_t)d * (4*HE_) * HE_;
        for (int s = tid; s < 32*(HE_/4); s += 256) {
            int c = s / (HE_/4), k4 = s % (HE_/4);
            int wr = (c >> 3) * HE_ + u0 + (c & 7);
            float4 v = *(const float4*)(wb + (size_t)wr*HE_ + k4*4);
            Bs[(k4*4+0)*34 + c] = v.x;
            Bs[(k4*4+1)*34 + c] = v.y;
            Bs[(k4*4+2)*34 + c] = v.z;
            Bs[(k4*4+3)*34 + c] = v.w;
        }
    }
    float* obase = layer ? g_enc : g_h1;
    __syncthreads();

    for (int t = 0; t < L_; t++) {
        const int t_eff = d ? (L_-1-t) : t;
        ull acc[8];
        #pragma unroll
        for (int i = 0; i < 8; i++) acc[i] = 0ull;

        if (t > 0) {
            const float* hin = g_eh[t & 1][d];
            float ra[8];
            {
                float4 h0 = __ldcg((const float4*)(hin + (size_t)lrow*HE_ + lk0));
                float4 h1 = __ldcg((const float4*)(hin + (size_t)lrow*HE_ + lk0 + 4));
                ra[0]=h0.x; ra[1]=h0.y; ra[2]=h0.z; ra[3]=h0.w;
                ra[4]=h1.x; ra[5]=h1.y; ra[6]=h1.z; ra[7]=h1.w;
            }
            #pragma unroll
            for (int i = 0; i < 8; i++) As[(lk0+i)*132 + lrow] = ra[i];
            __syncthreads();
            int buf = 0;
            #pragma unroll 1
            for (int kc = 0; kc < HE_; kc += 16) {
                if (kc + 16 < HE_) {
                    float4 h0 = __ldcg((const float4*)(hin + (size_t)lrow*HE_ + kc+16 + lk0));
                    float4 h1 = __ldcg((const float4*)(hin + (size_t)lrow*HE_ + kc+16 + lk0 + 4));
                    ra[0]=h0.x; ra[1]=h0.y; ra[2]=h0.z; ra[3]=h0.w;
                    ra[4]=h1.x; ra[5]=h1.y; ra[6]=h1.z; ra[7]=h1.w;
                }
                const float* ab = As + buf*2112 + t_r*8;
                const float* bb = Bs + kc*34 + 2*t_c;
                #pragma unroll
                for (int kk = 0; kk < 16; kk++) {
                    float4 a0 = *(const float4*)(ab + kk*132);
                    float4 a1 = *(const float4*)(ab + kk*132 + 4);
                    ull bp = *(const ull*)(bb + kk*34);
                    ull d0, d1, d2, d3, d4, d5, d6, d7;
                    asm("mov.b64 %0, {%1, %1};" : "=l"(d0) : "f"(a0.x));
                    asm("mov.b64 %0, {%1, %1};" : "=l"(d1) : "f"(a0.y));
                    asm("mov.b64 %0, {%1, %1};" : "=l"(d2) : "f"(a0.z));
                    asm("mov.b64 %0, {%1, %1};" : "=l"(d3) : "f"(a0.w));
                    asm("mov.b64 %0, {%1, %1};" : "=l"(d4) : "f"(a1.x));
                    asm("mov.b64 %0, {%1, %1};" : "=l"(d5) : "f"(a1.y));
                    asm("mov.b64 %0, {%1, %1};" : "=l"(d6) : "f"(a1.z));
                    asm("mov.b64 %0, {%1, %1};" : "=l"(d7) : "f"(a1.w));
                    fma2(acc[0], d0, bp);
                    fma2(acc[1], d1, bp);
                    fma2(acc[2], d2, bp);
                    fma2(acc[3], d3, bp);
                    fma2(acc[4], d4, bp);
                    fma2(acc[5], d5, bp);
                    fma2(acc[6], d6, bp);
                    fma2(acc[7], d7, bp);
                }
                if (kc + 16 < HE_) {
                    int nb = buf ^ 1;
                    #pragma unroll
                    for (int i = 0; i < 8; i++) As[nb*2112 + (lk0+i)*132 + lrow] = ra[i];
                    __syncthreads();
                    buf = nb;
                }
            }
        }
        #pragma unroll
        for (int i = 0; i < 8; i++) {
            float2 v = unpack2(acc[i]);
            gs[(t_r*8+i)*36 + 2*t_c]     = v.x;
            gs[(t_r*8+i)*36 + 2*t_c + 1] = v.y;
        }
        __syncthreads();
        {
            int row = tid >> 1;
            int uu0 = (tid & 1) * 4;
            int n = row;
            const float* Gp = g_G[d] + ((size_t)t_eff*N_ + n)*G4E_ + u0 + uu0;
            float4 Gi = *(const float4*)(Gp);
            float4 Gf = *(const float4*)(Gp + HE_);
            float4 Gc = *(const float4*)(Gp + 2*HE_);
            float4 Go = *(const float4*)(Gp + 3*HE_);
            float4 si = *(const float4*)&gs[row*36 + uu0];
            float4 sf = *(const float4*)&gs[row*36 + 8 + uu0];
            float4 sc = *(const float4*)&gs[row*36 + 16 + uu0];
            float4 so = *(const float4*)&gs[row*36 + 24 + uu0];
            float* cp = &g_ec[d][n*HE_ + u0 + uu0];
            float4 cv = (t > 0) ? *(const float4*)cp : make_float4(0.f,0.f,0.f,0.f);
            float4 cn, hn;
            cn.x = sigf(Gf.x+sf.x)*cv.x + sigf(Gi.x+si.x)*tanhf(Gc.x+sc.x);
            cn.y = sigf(Gf.y+sf.y)*cv.y + sigf(Gi.y+si.y)*tanhf(Gc.y+sc.y);
            cn.z = sigf(Gf.z+sf.z)*cv.z + sigf(Gi.z+si.z)*tanhf(Gc.z+sc.z);
            cn.w = sigf(Gf.w+sf.w)*cv.w + sigf(Gi.w+si.w)*tanhf(Gc.w+sc.w);
            hn.x = sigf(Go.x+so.x)*tanhf(cn.x);
            hn.y = sigf(Go.y+so.y)*tanhf(cn.y);
            hn.z = sigf(Go.z+so.z)*tanhf(cn.z);
            hn.w = sigf(Go.w+so.w)*tanhf(cn.w);
            *(float4*)cp = cn;
            *(float4*)&g_eh[1-(t&1)][d][n*HE_ + u0 + uu0] = hn;
            *(float4*)&obase[(size_t)t_eff*(N_*2*HE_) + (size_t)n*(2*HE_) + d*HE_ + u0 + uu0] = hn;
        }
        gridbar();
    }
}

// ---------------- decoder init ----------------
__global__ void k_dec_init()
{
    int i = blockIdx.x*blockDim.x + threadIdx.x;
    if (i < N_*HD_) {
        int n = i / HD_, k = i % HD_;
        g_dc[i] = g_enc[(size_t)n*(2*HE_) + HE_ + (k & (HE_-1))];
        g_dh[0][i] = 0.f;
    }
}

// ================= persistent decoder (R5 version) =================
__global__ __launch_bounds__(256) void k_decP(const float* __restrict__ dwhh,
        const float* __restrict__ dwih, const float* __restrict__ db,
        const float* __restrict__ ow, const float* __restrict__ obv,
        const int* __restrict__ tags, float* __restrict__ out)
{
    extern __shared__ float sm[];
    float* Bs = sm;                        // [1024][34]
    float* As = sm + 1024*34;              // [2][16][132]
    float* gs = As + 2*16*132;             // [128][36]
    float* hs  = As;                       // logits overlay [1024]
    float* red = As + 1024;                // [256]
    int*  redi = (int*)(red + 256);        // [128]

    const int b  = blockIdx.x;
    const int u0 = b * 8;
    const int tid = threadIdx.x;
    const int t_c = tid & 15, t_r = tid >> 4;
    const int lrow = tid >> 1, lk0 = (tid & 1) * 8;

    for (int s = tid; s < 32*(HD_/4); s += 256) {
        int c = s / (HD_/4), k4 = s % (HD_/4);
        int wr = (c >> 3) * HD_ + u0 + (c & 7);
        float4 v = *(const float4*)(dwhh + (size_t)wr*HD_ + k4*4);
        Bs[(k4*4+0)*34 + c] = v.x;
        Bs[(k4*4+1)*34 + c] = v.y;
        Bs[(k4*4+2)*34 + c] = v.z;
        Bs[(k4*4+3)*34 + c] = v.w;
    }
    __syncthreads();

    for (int t = 0; t < L_; t++) {
        const int ph = t & 1;
        ull acc[8];
        #pragma unroll
        for (int i = 0; i < 8; i++) acc[i] = 0ull;
        {
            const float* hin  = g_dh[ph];
            const float* encT = g_enc + (size_t)t * (N_*HD_);
            const size_t abase = (size_t)lrow*HD_ + lk0;
            float ra[8];
            {
                float4 h0 = __ldcg((const float4*)(hin + abase));
                float4 h1 = __ldcg((const float4*)(hin + abase + 4));
                float4 e0 = *(const float4*)(encT + abase);
                float4 e1 = *(const float4*)(encT + abase + 4);
                ra[0]=h0.x+e0.x; ra[1]=h0.y+e0.y; ra[2]=h0.z+e0.z; ra[3]=h0.w+e0.w;
                ra[4]=h1.x+e1.x; ra[5]=h1.y+e1.y; ra[6]=h1.z+e1.z; ra[7]=h1.w+e1.w;
            }
            #pragma unroll
            for (int i = 0; i < 8; i++) As[(lk0+i)*132 + lrow] = ra[i];
            __syncthreads();
            int buf = 0;
            #pragma unroll 1
            for (int kc = 0; kc < HD_; kc += 16) {
                if (kc + 16 < HD_) {
                    float4 h0 = __ldcg((const float4*)(hin + abase + kc+16));
                    float4 h1 = __ldcg((const float4*)(hin + abase + kc+16 + 4));
                    float4 e0 = *(const float4*)(encT + abase + kc+16);
                    float4 e1 = *(const float4*)(encT + abase + kc+16 + 4);
                    ra[0]=h0.x+e0.x; ra[1]=h0.y+e0.y; ra[2]=h0.z+e0.z; ra[3]=h0.w+e0.w;
                    ra[4]=h1.x+e1.x; ra[5]=h1.y+e1.y; ra[6]=h1.z+e1.z; ra[7]=h1.w+e1.w;
                }
                const float* ab = As + buf*2112 + t_r*8;
                const float* bb = Bs + kc*34 + 2*t_c;
                #pragma unroll
                for (int kk = 0; kk < 16; kk++) {
                    float4 a0 = *(const float4*)(ab + kk*132);
                    float4 a1 = *(const float4*)(ab + kk*132 + 4);
                    ull bp = *(const ull*)(bb + kk*34);
                    ull d0, d1, d2, d3, d4, d5, d6, d7;
                    asm("mov.b64 %0, {%1, %1};" : "=l"(d0) : "f"(a0.x));
                    asm("mov.b64 %0, {%1, %1};" : "=l"(d1) : "f"(a0.y));
                    asm("mov.b64 %0, {%1, %1};" : "=l"(d2) : "f"(a0.z));
                    asm("mov.b64 %0, {%1, %1};" : "=l"(d3) : "f"(a0.w));
                    asm("mov.b64 %0, {%1, %1};" : "=l"(d4) : "f"(a1.x));
                    asm("mov.b64 %0, {%1, %1};" : "=l"(d5) : "f"(a1.y));
                    asm("mov.b64 %0, {%1, %1};" : "=l"(d6) : "f"(a1.z));
                    asm("mov.b64 %0, {%1, %1};" : "=l"(d7) : "f"(a1.w));
                    fma2(acc[0], d0, bp);
                    fma2(acc[1], d1, bp);
                    fma2(acc[2], d2, bp);
                    fma2(acc[3], d3, bp);
                    fma2(acc[4], d4, bp);
                    fma2(acc[5], d5, bp);
                    fma2(acc[6], d6, bp);
                    fma2(acc[7], d7, bp);
                }
                if (kc + 16 < HD_) {
                    int nb = buf ^ 1;
                    #pragma unroll
                    for (int i = 0; i < 8; i++) As[nb*2112 + (lk0+i)*132 + lrow] = ra[i];
                    __syncthreads();
                    buf = nb;
                }
            }
        }
        #pragma unroll
        for (int i = 0; i < 8; i++) {
            float2 v = unpack2(acc[i]);
            gs[(t_r*8+i)*36 + 2*t_c]     = v.x;
            gs[(t_r*8+i)*36 + 2*t_c + 1] = v.y;
        }
        __syncthreads();
        {
            int row = tid >> 1;
            int uu0 = (tid & 1) * 4;
            int n = row;
            int am = (t > 0) ? __ldcg(&g_amax[n]) : 0;
            float4 si = *(const float4*)&gs[row*36 + uu0];
            float4 sf = *(const float4*)&gs[row*36 + 8 + uu0];
            float4 sc = *(const float4*)&gs[row*36 + 16 + uu0];
            float4 so = *(const float4*)&gs[row*36 + 24 + uu0];
            float4 bi = *(const float4*)(db + u0 + uu0);
            float4 bf = *(const float4*)(db + HD_ + u0 + uu0);
            float4 bc = *(const float4*)(db + 2*HD_ + u0 + uu0);
            float4 bo = *(const float4*)(db + 3*HD_ + u0 + uu0);
            float wi[4][4];
            #pragma unroll
            for (int g = 0; g < 4; g++)
                #pragma unroll
                for (int e = 0; e < 4; e++)
                    wi[g][e] = (t > 0) ? __ldg(dwih + (size_t)(g*HD_ + u0 + uu0 + e)*T_ + am) : 0.f;
            float gi[4] = {si.x+bi.x+wi[0][0], si.y+bi.y+wi[0][1], si.z+bi.z+wi[0][2], si.w+bi.w+wi[0][3]};
            float gf[4] = {sf.x+bf.x+wi[1][0], sf.y+bf.y+wi[1][1], sf.z+bf.z+wi[1][2], sf.w+bf.w+wi[1][3]};
            float gc[4] = {sc.x+bc.x+wi[2][0], sc.y+bc.y+wi[2][1], sc.z+bc.z+wi[2][2], sc.w+bc.w+wi[2][3]};
            float go[4] = {so.x+bo.x+wi[3][0], so.y+bo.y+wi[3][1], so.z+bo.z+wi[3][2], so.w+bo.w+wi[3][3]};
            float* cp = &g_dc[n*HD_ + u0 + uu0];
            float4 cv = *(const float4*)cp;
            float4 cn, hn;
            cn.x = sigf(gf[0])*cv.x + sigf(gi[0])*tanhf(gc[0]);
            cn.y = sigf(gf[1])*cv.y + sigf(gi[1])*tanhf(gc[1]);
            cn.z = sigf(gf[2])*cv.z + sigf(gi[2])*tanhf(gc[2]);
            cn.w = sigf(gf[3])*cv.w + sigf(gi[3])*tanhf(gc[3]);
            hn.x = sigf(go[0])*tanhf(cn.x);
            hn.y = sigf(go[1])*tanhf(cn.y);
            hn.z = sigf(go[2])*tanhf(cn.z);
            hn.w = sigf(go[3])*tanhf(cn.w);
            *(float4*)cp = cn;
            *(float4*)&g_dh[1-ph][n*HD_ + u0 + uu0] = hn;
        }
        gridbar();
        // ---- logits / softmax / argmax: block b = sample n ----
        {
            const int n = b;
            const int j = tid & 127;
            const int half = tid >> 7;
            const float* hsrc = g_dh[1-ph] + (size_t)n*HD_;
            for (int k = tid; k < HD_; k += 256) hs[k] = __ldcg(hsrc + k);
            __syncthreads();
            ull s0 = 0ull, s1 = 0ull;
            const float* wrow = ow + (size_t)j*HD_ + half*512;
            const float* hh = hs + half*512;
            #pragma unroll 8
            for (int k = 0; k < 512; k += 8) {
                ulonglong2 w01 = *(const ulonglong2*)(wrow + k);
                ulonglong2 w23 = *(const ulonglong2*)(wrow + k + 4);
                ulonglong2 h01 = *(const ulonglong2*)(hh + k);
                ulonglong2 h23 = *(const ulonglong2*)(hh + k + 4);
                fma2(s0, w01.x, h01.x);
                fma2(s1, w01.y, h01.y);
                fma2(s0, w23.x, h23.x);
                fma2(s1, w23.y, h23.y);
            }
            float2 q0 = unpack2(s0), q1 = unpack2(s1);
            red[tid] = (q0.x + q0.y) + (q1.x + q1.y);
            __syncthreads();
            float accv = obv[j] + red[j] + red[j+128];
            __syncthreads();
            if (half == 0) red[j] = accv;
            __syncthreads();
            for (int s = 64; s > 0; s >>= 1) { if (tid < s) red[tid] = fmaxf(red[tid], red[tid+s]); __syncthreads(); }
            float mx = red[0]; __syncthreads();
            float ev = expf(accv - mx);
            if (half == 0) red[j] = ev;
            __syncthreads();
            for (int s = 64; s > 0; s >>= 1) { if (tid < s) red[tid] += red[tid+s]; __syncthreads(); }
            float sum = red[0];
            if (half == 0) out[((size_t)n*L_ + t)*T_ + j] = ev / sum;
            int tag = tags[n*L_ + t];
            if (tid == tag) g_lterm[t*N_ + n] = -(accv - mx - logf(sum)) / (float)N_;
            __syncthreads();
            if (half == 0) { red[j] = accv; redi[j] = j; }
            __syncthreads();
            for (int s = 64; s > 0; s >>= 1) {
                if (tid < s) {
                    float o = red[tid+s]; int oi = redi[tid+s];
                    if (o > red[tid] || (o == red[tid] && oi < redi[tid])) { red[tid] = o; redi[tid] = oi; }
                }
                __syncthreads();
            }
            if (tid == 0) g_amax[n] = redi[0];
        }
        gridbar();
    }
}

// ---------------- deterministic loss reduction ----------------
__global__ void k_loss(float* __restrict__ out)
{
    __shared__ float red[256];
    float s = 0.f;
    for (int i = threadIdx.x; i < L_*N_; i += 256) s += g_lterm[i];
    red[threadIdx.x] = s; __syncthreads();
    for (int st = 128; st > 0; st >>= 1) {
        if (threadIdx.x < st) red[threadIdx.x] += red[threadIdx.x + st];
        __syncthreads();
    }
    if (threadIdx.x == 0) out[(size_t)N_*L_*T_] = red[0];
}

// ---------------- launcher ----------------
#define ENC_SMEM ((512*34 + 2*16*132 + 128*36)*4)
#define DEC_SMEM ((1024*34 + 2*16*132 + 128*36)*4)

extern "C" void kernel_launch(void* const* d_in, const int* in_sizes, int n_in,
                              void* d_out, int out_size)
{
    const int*   ids    = (const int*)  d_in[0];
    const int*   tags   = (const int*)  d_in[1];
    const float* embed  = (const float*)d_in[2];
    const float* e0_wih = (const float*)d_in[3];
    const float* e0_whh = (const float*)d_in[4];
    const float* e0_b   = (const float*)d_in[5];
    const float* e1_wih = (const float*)d_in[6];
    const float* e1_whh = (const float*)d_in[7];
    const float* e1_b   = (const float*)d_in[8];
    const float* dwih   = (const float*)d_in[9];
    const float* dwhh   = (const float*)d_in[10];
    const float* db     = (const float*)d_in[11];
    const float* ow     = (const float*)d_in[12];
    const float* obv    = (const float*)d_in[13];
    float* out = (float*)d_out;

    cudaFuncSetAttribute(k_encP, cudaFuncAttributeMaxDynamicSharedMemorySize, ENC_SMEM);
    cudaFuncSetAttribute(k_decP, cudaFuncAttributeMaxDynamicSharedMemorySize, DEC_SMEM);

    // 1. embedding
    k_embed<<<(LN_*E_/4 + 255)/256, 256>>>(ids, embed);

    // 2. enc0
    {
        dim3 gg(G4E_/128, LN_/128, 2);
        k_gemm_bias<<<gg, 256>>>(0, e0_wih, e0_b, E_);
    }
    k_encP<<<NB_, 256, ENC_SMEM>>>(0, e0_whh);

    // 3. enc1
    {
        dim3 gg(G4E_/128, LN_/128, 2);
        k_gemm_bias<<<gg, 256>>>(1, e1_wih, e1_b, 2*HE_);
    }
    k_encP<<<NB_, 256, ENC_SMEM>>>(1, e1_whh);

    // 4. decoder
    k_dec_init<<<(N_*HD_ + 255)/256, 256>>>();
    k_decP<<<NB_, 256, DEC_SMEM>>>(dwhh, dwih, db, ow, obv, tags, out);

    // 5. loss
    k_loss<<<1, 256>>>(out);
}

// round 8
// speedup vs baseline: 1.4768x; 1.4768x over previous
#include <cuda_runtime.h>

typedef unsigned long long ull;

#define N_ 128
#define L_ 160
#define E_ 512
#define HE_ 512
#define HD_ 1024
#define T_ 128
#define LN_ (L_*N_)
#define G4E_ 2048
#define NB_ 128u

// ---------------- scratch (device globals) ----------------
__device__ __align__(16) float g_xs[LN_*E_];
__device__ __align__(16) float g_G[2][(size_t)LN_*G4E_];
__device__ __align__(16) float g_h1[(size_t)LN_*2*HE_];
__device__ __align__(16) float g_enc[(size_t)LN_*2*HE_];
__device__ __align__(16) float g_eh[2][2][N_*HE_];   // [phase][dir]
__device__ __align__(16) float g_ec[2][N_*HE_];      // [dir]
__device__ __align__(16) float g_dh[2][N_*HD_];
__device__ __align__(16) float g_dc[N_*HD_];
__device__ int   g_amax[N_];
__device__ float g_lterm[L_*N_];

__device__ unsigned g_bcnt = 0;
__device__ volatile unsigned g_bgen = 0;

__device__ __forceinline__ void fma2(ull& d, ull a, ull b){
    asm("fma.rn.f32x2 %0, %1, %2, %0;" : "+l"(d) : "l"(a), "l"(b));
}
__device__ __forceinline__ ull dup2(float x){
    ull r; asm("mov.b64 %0, {%1, %1};" : "=l"(r) : "f"(x)); return r;
}
__device__ __forceinline__ float2 unpack2(ull v){
    float2 r; asm("mov.b64 {%0, %1}, %2;" : "=f"(r.x), "=f"(r.y) : "l"(v)); return r;
}
__device__ __forceinline__ float sigf(float x){ return 1.f/(1.f+expf(-x)); }

__device__ __forceinline__ void gridbar(){
    __syncthreads();
    if (threadIdx.x == 0) {
        unsigned g = g_bgen;
        __threadfence();
        if (atomicAdd(&g_bcnt, 1u) == NB_ - 1u) {
            atomicExch(&g_bcnt, 0u);
            __threadfence();
            g_bgen = g + 1u;
        } else {
            while (g_bgen == g) { }
        }
        __threadfence();
    }
    __syncthreads();
}

// ---------------- embedding ----------------
__global__ void k_embed(const int* __restrict__ ids, const float* __restrict__ embed)
{
    int i = blockIdx.x*blockDim.x + threadIdx.x;
    const int tot = LN_*E_/4;
    if (i >= tot) return;
    int e4 = i % (E_/4);
    int ln = i / (E_/4);
    int l = ln / N_, n = ln % N_;
    int id = ids[n*L_ + l];
    reinterpret_cast<float4*>(g_xs)[i] =
        reinterpret_cast<const float4*>(embed + (size_t)id*E_)[e4];
}

// ---------------- big input GEMM (exact R5 version, 29.3ms config) ----------------
__global__ __launch_bounds__(256) void k_gemm_bias(int asel, const float* __restrict__ Ball,
                                                   const float* __restrict__ biasall, int K)
{
    const float* A = asel ? g_h1 : g_xs;
    int z = blockIdx.z;
    const float* B = Ball + (size_t)z * G4E_ * K;
    const float* bias = biasall + z * G4E_;
    float* C = g_G[z];
    int m0 = blockIdx.y * 128, n0 = blockIdx.x * 128;
    __shared__ float2 As2[8][132];
    __shared__ float  Bs[8][132];
    int tid = threadIdx.x;
    int lr = tid >> 1, lk = (tid & 1) * 4;
    int ry = (tid >> 4) * 8, cx = (tid & 15) * 8;
    ull acc[8][4];
    #pragma unroll
    for (int i = 0; i < 8; i++)
        #pragma unroll
        for (int j = 0; j < 4; j++) acc[i][j] = 0ull;
    const float* Arow = A + (size_t)(m0+lr)*K + lk;
    const float* Brow = B + (size_t)(n0+lr)*K + lk;
    for (int kc = 0; kc < K; kc += 8) {
        float4 av = *(const float4*)(Arow + kc);
        float4 bv = *(const float4*)(Brow + kc);
        __syncthreads();
        As2[lk+0][lr]=make_float2(av.x,av.x); As2[lk+1][lr]=make_float2(av.y,av.y);
        As2[lk+2][lr]=make_float2(av.z,av.z); As2[lk+3][lr]=make_float2(av.w,av.w);
        Bs[lk+0][lr]=bv.x; Bs[lk+1][lr]=bv.y; Bs[lk+2][lr]=bv.z; Bs[lk+3][lr]=bv.w;
        __syncthreads();
        #pragma unroll
        for (int kk = 0; kk < 8; kk++) {
            ulonglong2 a01 = *(const ulonglong2*)&As2[kk][ry+0];
            ulonglong2 a23 = *(const ulonglong2*)&As2[kk][ry+2];
            ulonglong2 a45 = *(const ulonglong2*)&As2[kk][ry+4];
            ulonglong2 a67 = *(const ulonglong2*)&As2[kk][ry+6];
            ulonglong2 b01 = *(const ulonglong2*)&Bs[kk][cx];
            ulonglong2 b23 = *(const ulonglong2*)&Bs[kk][cx+4];
            ull a[8] = {a01.x,a01.y,a23.x,a23.y,a45.x,a45.y,a67.x,a67.y};
            #pragma unroll
            for (int i = 0; i < 8; i++) {
                fma2(acc[i][0], a[i], b01.x);
                fma2(acc[i][1], a[i], b01.y);
                fma2(acc[i][2], a[i], b23.x);
                fma2(acc[i][3], a[i], b23.y);
            }
        }
    }
    #pragma unroll
    for (int i = 0; i < 8; i++) {
        float* Cp = C + (size_t)(m0+ry+i)*G4E_ + n0 + cx;
        #pragma unroll
        for (int j = 0; j < 4; j++) {
            float2 v = unpack2(acc[i][j]);
            Cp[2*j+0] = v.x + bias[n0+cx+2*j+0];
            Cp[2*j+1] = v.y + bias[n0+cx+2*j+1];
        }
    }
}

// ================= persistent encoder layer (row-pair f32x2 packing) =================
// acc[j]   j=0..3 : row-pairs (2j,2j+1) of col 2*t_c
// acc[4+j]        : row-pairs of col 2*t_c+1
__global__ __launch_bounds__(256) void k_encP(int layer, const float* __restrict__ whh_all)
{
    extern __shared__ float sm[];
    float* Bs = sm;                        // [512][34]
    float* As = sm + 512*34;               // [2][16][132]
    float* gs = As + 2*16*132;             // [128][36]

    const int b  = blockIdx.x;
    const int d  = b >> 6;
    const int u0 = (b & 63) * 8;
    const int tid = threadIdx.x;
    const int t_c = tid & 15, t_r = tid >> 4;
    const int lrow = tid >> 1, lk0 = (tid & 1) * 8;

    {
        const float* wb = whh_all + (size_t)d * (4*HE_) * HE_;
        for (int s = tid; s < 32*(HE_/4); s += 256) {
            int c = s / (HE_/4), k4 = s % (HE_/4);
            int wr = (c >> 3) * HE_ + u0 + (c & 7);
            float4 v = *(const float4*)(wb + (size_t)wr*HE_ + k4*4);
            Bs[(k4*4+0)*34 + c] = v.x;
            Bs[(k4*4+1)*34 + c] = v.y;
            Bs[(k4*4+2)*34 + c] = v.z;
            Bs[(k4*4+3)*34 + c] = v.w;
        }
    }
    float* obase = layer ? g_enc : g_h1;
    __syncthreads();

    for (int t = 0; t < L_; t++) {
        const int t_eff = d ? (L_-1-t) : t;
        ull acc[8];
        #pragma unroll
        for (int i = 0; i < 8; i++) acc[i] = 0ull;

        if (t > 0) {
            const float* hin = g_eh[t & 1][d];
            float ra[8];
            {
                float4 h0 = __ldcg((const float4*)(hin + (size_t)lrow*HE_ + lk0));
                float4 h1 = __ldcg((const float4*)(hin + (size_t)lrow*HE_ + lk0 + 4));
                ra[0]=h0.x; ra[1]=h0.y; ra[2]=h0.z; ra[3]=h0.w;
                ra[4]=h1.x; ra[5]=h1.y; ra[6]=h1.z; ra[7]=h1.w;
            }
            #pragma unroll
            for (int i = 0; i < 8; i++) As[(lk0+i)*132 + lrow] = ra[i];
            __syncthreads();
            int buf = 0;
            #pragma unroll 1
            for (int kc = 0; kc < HE_; kc += 16) {
                if (kc + 16 < HE_) {
                    float4 h0 = __ldcg((const float4*)(hin + (size_t)lrow*HE_ + kc+16 + lk0));
                    float4 h1 = __ldcg((const float4*)(hin + (size_t)lrow*HE_ + kc+16 + lk0 + 4));
                    ra[0]=h0.x; ra[1]=h0.y; ra[2]=h0.z; ra[3]=h0.w;
                    ra[4]=h1.x; ra[5]=h1.y; ra[6]=h1.z; ra[7]=h1.w;
                }
                const float* ab = As + buf*2112 + t_r*8;
                const float* bb = Bs + kc*34 + 2*t_c;
                #pragma unroll
                for (int kk = 0; kk < 16; kk++) {
                    ulonglong2 aA = *(const ulonglong2*)(ab + kk*132);      // rows 0-3 (2 pairs)
                    ulonglong2 aB = *(const ulonglong2*)(ab + kk*132 + 4);  // rows 4-7
                    float2 bv = *(const float2*)(bb + kk*34);
                    ull b0 = dup2(bv.x);
                    ull b1 = dup2(bv.y);
                    fma2(acc[0], aA.x, b0);
                    fma2(acc[1], aA.y, b0);
                    fma2(acc[2], aB.x, b0);
                    fma2(acc[3], aB.y, b0);
                    fma2(acc[4], aA.x, b1);
                    fma2(acc[5], aA.y, b1);
                    fma2(acc[6], aB.x, b1);
                    fma2(acc[7], aB.y, b1);
                }
                if (kc + 16 < HE_) {
                    int nb = buf ^ 1;
                    #pragma unroll
                    for (int i = 0; i < 8; i++) As[nb*2112 + (lk0+i)*132 + lrow] = ra[i];
                    __syncthreads();
                    buf = nb;
                }
            }
        }
        #pragma unroll
        for (int p = 0; p < 4; p++) {
            float2 v0 = unpack2(acc[p]);      // col 2t_c,  rows 2p/2p+1
            float2 v1 = unpack2(acc[4+p]);    // col 2t_c+1
            *(float2*)&gs[(t_r*8+2*p)*36   + 2*t_c] = make_float2(v0.x, v1.x);
            *(float2*)&gs[(t_r*8+2*p+1)*36 + 2*t_c] = make_float2(v0.y, v1.y);
        }
        __syncthreads();
        {
            int row = tid >> 1;
            int uu0 = (tid & 1) * 4;
            int n = row;
            const float* Gp = g_G[d] + ((size_t)t_eff*N_ + n)*G4E_ + u0 + uu0;
            float4 Gi = *(const float4*)(Gp);
            float4 Gf = *(const float4*)(Gp + HE_);
            float4 Gc = *(const float4*)(Gp + 2*HE_);
            float4 Go = *(const float4*)(Gp + 3*HE_);
            float4 si = *(const float4*)&gs[row*36 + uu0];
            float4 sf = *(const float4*)&gs[row*36 + 8 + uu0];
            float4 sc = *(const float4*)&gs[row*36 + 16 + uu0];
            float4 so = *(const float4*)&gs[row*36 + 24 + uu0];
            float* cp = &g_ec[d][n*HE_ + u0 + uu0];
            float4 cv = (t > 0) ? *(const float4*)cp : make_float4(0.f,0.f,0.f,0.f);
            float4 cn, hn;
            cn.x = sigf(Gf.x+sf.x)*cv.x + sigf(Gi.x+si.x)*tanhf(Gc.x+sc.x);
            cn.y = sigf(Gf.y+sf.y)*cv.y + sigf(Gi.y+si.y)*tanhf(Gc.y+sc.y);
            cn.z = sigf(Gf.z+sf.z)*cv.z + sigf(Gi.z+si.z)*tanhf(Gc.z+sc.z);
            cn.w = sigf(Gf.w+sf.w)*cv.w + sigf(Gi.w+si.w)*tanhf(Gc.w+sc.w);
            hn.x = sigf(Go.x+so.x)*tanhf(cn.x);
            hn.y = sigf(Go.y+so.y)*tanhf(cn.y);
            hn.z = sigf(Go.z+so.z)*tanhf(cn.z);
            hn.w = sigf(Go.w+so.w)*tanhf(cn.w);
            *(float4*)cp = cn;
            *(float4*)&g_eh[1-(t&1)][d][n*HE_ + u0 + uu0] = hn;
            *(float4*)&obase[(size_t)t_eff*(N_*2*HE_) + (size_t)n*(2*HE_) + d*HE_ + u0 + uu0] = hn;
        }
        gridbar();
    }
}

// ---------------- decoder init ----------------
__global__ void k_dec_init()
{
    int i = blockIdx.x*blockDim.x + threadIdx.x;
    if (i < N_*HD_) {
        int n = i / HD_, k = i % HD_;
        g_dc[i] = g_enc[(size_t)n*(2*HE_) + HE_ + (k & (HE_-1))];
        g_dh[0][i] = 0.f;
    }
}

// ================= persistent decoder (row-pair f32x2 packing) =================
__global__ __launch_bounds__(256) void k_decP(const float* __restrict__ dwhh,
        const float* __restrict__ dwih, const float* __restrict__ db,
        const float* __restrict__ ow, const float* __restrict__ obv,
        const int* __restrict__ tags, float* __restrict__ out)
{
    extern __shared__ float sm[];
    float* Bs = sm;                        // [1024][34]
    float* As = sm + 1024*34;              // [2][16][132]
    float* gs = As + 2*16*132;             // [128][36]
    float* hs  = As;                       // logits overlay [1024]
    float* red = As + 1024;                // [256]
    int*  redi = (int*)(red + 256);        // [128]

    const int b  = blockIdx.x;
    const int u0 = b * 8;
    const int tid = threadIdx.x;
    const int t_c = tid & 15, t_r = tid >> 4;
    const int lrow = tid >> 1, lk0 = (tid & 1) * 8;

    for (int s = tid; s < 32*(HD_/4); s += 256) {
        int c = s / (HD_/4), k4 = s % (HD_/4);
        int wr = (c >> 3) * HD_ + u0 + (c & 7);
        float4 v = *(const float4*)(dwhh + (size_t)wr*HD_ + k4*4);
        Bs[(k4*4+0)*34 + c] = v.x;
        Bs[(k4*4+1)*34 + c] = v.y;
        Bs[(k4*4+2)*34 + c] = v.z;
        Bs[(k4*4+3)*34 + c] = v.w;
    }
    __syncthreads();

    for (int t = 0; t < L_; t++) {
        const int ph = t & 1;
        ull acc[8];
        #pragma unroll
        for (int i = 0; i < 8; i++) acc[i] = 0ull;
        {
            const float* hin  = g_dh[ph];
            const float* encT = g_enc + (size_t)t * (N_*HD_);
            const size_t abase = (size_t)lrow*HD_ + lk0;
            float ra[8];
            {
                float4 h0 = __ldcg((const float4*)(hin + abase));
                float4 h1 = __ldcg((const float4*)(hin + abase + 4));
                float4 e0 = *(const float4*)(encT + abase);
                float4 e1 = *(const float4*)(encT + abase + 4);
                ra[0]=h0.x+e0.x; ra[1]=h0.y+e0.y; ra[2]=h0.z+e0.z; ra[3]=h0.w+e0.w;
                ra[4]=h1.x+e1.x; ra[5]=h1.y+e1.y; ra[6]=h1.z+e1.z; ra[7]=h1.w+e1.w;
            }
            #pragma unroll
            for (int i = 0; i < 8; i++) As[(lk0+i)*132 + lrow] = ra[i];
            __syncthreads();
            int buf = 0;
            #pragma unroll 1
            for (int kc = 0; kc < HD_; kc += 16) {
                if (kc + 16 < HD_) {
                    float4 h0 = __ldcg((const float4*)(hin + abase + kc+16));
                    float4 h1 = __ldcg((const float4*)(hin + abase + kc+16 + 4));
                    float4 e0 = *(const float4*)(encT + abase + kc+16);
                    float4 e1 = *(const float4*)(encT + abase + kc+16 + 4);
                    ra[0]=h0.x+e0.x; ra[1]=h0.y+e0.y; ra[2]=h0.z+e0.z; ra[3]=h0.w+e0.w;
                    ra[4]=h1.x+e1.x; ra[5]=h1.y+e1.y; ra[6]=h1.z+e1.z; ra[7]=h1.w+e1.w;
                }
                const float* ab = As + buf*2112 + t_r*8;
                const float* bb = Bs + kc*34 + 2*t_c;
                #pragma unroll
                for (int kk = 0; kk < 16; kk++) {
                    ulonglong2 aA = *(const ulonglong2*)(ab + kk*132);
                    ulonglong2 aB = *(const ulonglong2*)(ab + kk*132 + 4);
                    float2 bv = *(const float2*)(bb + kk*34);
                    ull b0 = dup2(bv.x);
                    ull b1 = dup2(bv.y);
                    fma2(acc[0], aA.x, b0);
                    fma2(acc[1], aA.y, b0);
                    fma2(acc[2], aB.x, b0);
                    fma2(acc[3], aB.y, b0);
                    fma2(acc[4], aA.x, b1);
                    fma2(acc[5], aA.y, b1);
                    fma2(acc[6], aB.x, b1);
                    fma2(acc[7], aB.y, b1);
                }
                if (kc + 16 < HD_) {
                    int nb = buf ^ 1;
                    #pragma unroll
                    for (int i = 0; i < 8; i++) As[nb*2112 + (lk0+i)*132 + lrow] = ra[i];
                    __syncthreads();
                    buf = nb;
                }
            }
        }
        #pragma unroll
        for (int p = 0; p < 4; p++) {
            float2 v0 = unpack2(acc[p]);
            float2 v1 = unpack2(acc[4+p]);
            *(float2*)&gs[(t_r*8+2*p)*36   + 2*t_c] = make_float2(v0.x, v1.x);
            *(float2*)&gs[(t_r*8+2*p+1)*36 + 2*t_c] = make_float2(v0.y, v1.y);
        }
        __syncthreads();
        {
            int row = tid >> 1;
            int uu0 = (tid & 1) * 4;
            int n = row;
            int am = (t > 0) ? __ldcg(&g_amax[n]) : 0;
            float4 si = *(const float4*)&gs[row*36 + uu0];
            float4 sf = *(const float4*)&gs[row*36 + 8 + uu0];
            float4 sc = *(const float4*)&gs[row*36 + 16 + uu0];
            float4 so = *(const float4*)&gs[row*36 + 24 + uu0];
            float4 bi = *(const float4*)(db + u0 + uu0);
            float4 bf = *(const float4*)(db + HD_ + u0 + uu0);
            float4 bc = *(const float4*)(db + 2*HD_ + u0 + uu0);
            float4 bo = *(const float4*)(db + 3*HD_ + u0 + uu0);
            float wi[4][4];
            #pragma unroll
            for (int g = 0; g < 4; g++)
                #pragma unroll
                for (int e = 0; e < 4; e++)
                    wi[g][e] = (t > 0) ? __ldg(dwih + (size_t)(g*HD_ + u0 + uu0 + e)*T_ + am) : 0.f;
            float gi[4] = {si.x+bi.x+wi[0][0], si.y+bi.y+wi[0][1], si.z+bi.z+wi[0][2], si.w+bi.w+wi[0][3]};
            float gf[4] = {sf.x+bf.x+wi[1][0], sf.y+bf.y+wi[1][1], sf.z+bf.z+wi[1][2], sf.w+bf.w+wi[1][3]};
            float gc[4] = {sc.x+bc.x+wi[2][0], sc.y+bc.y+wi[2][1], sc.z+bc.z+wi[2][2], sc.w+bc.w+wi[2][3]};
            float go[4] = {so.x+bo.x+wi[3][0], so.y+bo.y+wi[3][1], so.z+bo.z+wi[3][2], so.w+bo.w+wi[3][3]};
            float* cp = &g_dc[n*HD_ + u0 + uu0];
            float4 cv = *(const float4*)cp;
            float4 cn, hn;
            cn.x = sigf(gf[0])*cv.x + sigf(gi[0])*tanhf(gc[0]);
            cn.y = sigf(gf[1])*cv.y + sigf(gi[1])*tanhf(gc[1]);
            cn.z = sigf(gf[2])*cv.z + sigf(gi[2])*tanhf(gc[2]);
            cn.w = sigf(gf[3])*cv.w + sigf(gi[3])*tanhf(gc[3]);
            hn.x = sigf(go[0])*tanhf(cn.x);
            hn.y = sigf(go[1])*tanhf(cn.y);
            hn.z = sigf(go[2])*tanhf(cn.z);
            hn.w = sigf(go[3])*tanhf(cn.w);
            *(float4*)cp = cn;
            *(float4*)&g_dh[1-ph][n*HD_ + u0 + uu0] = hn;
        }
        gridbar();
        // ---- logits / softmax / argmax: block b = sample n ----
        {
            const int n = b;
            const int j = tid & 127;
            const int half = tid >> 7;
            const float* hsrc = g_dh[1-ph] + (size_t)n*HD_;
            for (int k = tid; k < HD_; k += 256) hs[k] = __ldcg(hsrc + k);
            __syncthreads();
            ull s0 = 0ull, s1 = 0ull;
            const float* wrow = ow + (size_t)j*HD_ + half*512;
            const float* hh = hs + half*512;
            #pragma unroll 8
            for (int k = 0; k < 512; k += 8) {
                ulonglong2 w01 = *(const ulonglong2*)(wrow + k);
                ulonglong2 w23 = *(const ulonglong2*)(wrow + k + 4);
                ulonglong2 h01 = *(const ulonglong2*)(hh + k);
                ulonglong2 h23 = *(const ulonglong2*)(hh + k + 4);
                fma2(s0, w01.x, h01.x);
                fma2(s1, w01.y, h01.y);
                fma2(s0, w23.x, h23.x);
                fma2(s1, w23.y, h23.y);
            }
            float2 q0 = unpack2(s0), q1 = unpack2(s1);
            red[tid] = (q0.x + q0.y) + (q1.x + q1.y);
            __syncthreads();
            float accv = obv[j] + red[j] + red[j+128];
            __syncthreads();
            if (half == 0) red[j] = accv;
            __syncthreads();
            for (int s = 64; s > 0; s >>= 1) { if (tid < s) red[tid] = fmaxf(red[tid], red[tid+s]); __syncthreads(); }
            float mx = red[0]; __syncthreads();
            float ev = expf(accv - mx);
            if (half == 0) red[j] = ev;
            __syncthreads();
            for (int s = 64; s > 0; s >>= 1) { if (tid < s) red[tid] += red[tid+s]; __syncthreads(); }
            float sum = red[0];
            if (half == 0) out[((size_t)n*L_ + t)*T_ + j] = ev / sum;
            int tag = tags[n*L_ + t];
            if (tid == tag) g_lterm[t*N_ + n] = -(accv - mx - logf(sum)) / (float)N_;
            __syncthreads();
            if (half == 0) { red[j] = accv; redi[j] = j; }
            __syncthreads();
            for (int s = 64; s > 0; s >>= 1) {
                if (tid < s) {
                    float o = red[tid+s]; int oi = redi[tid+s];
                    if (o > red[tid] || (o == red[tid] && oi < redi[tid])) { red[tid] = o; redi[tid] = oi; }
                }
                __syncthreads();
            }
            if (tid == 0) g_amax[n] = redi[0];
        }
        gridbar();
    }
}

// ---------------- deterministic loss reduction ----------------
__global__ void k_loss(float* __restrict__ out)
{
    __shared__ float red[256];
    float s = 0.f;
    for (int i = threadIdx.x; i < L_*N_; i += 256) s += g_lterm[i];
    red[threadIdx.x] = s; __syncthreads();
    for (int st = 128; st > 0; st >>= 1) {
        if (threadIdx.x < st) red[threadIdx.x] += red[threadIdx.x + st];
        __syncthreads();
    }
    if (threadIdx.x == 0) out[(size_t)N_*L_*T_] = red[0];
}

// ---------------- launcher ----------------
#define ENC_SMEM ((512*34 + 2*16*132 + 128*36)*4)
#define DEC_SMEM ((1024*34 + 2*16*132 + 128*36)*4)

extern "C" void kernel_launch(void* const* d_in, const int* in_sizes, int n_in,
                              void* d_out, int out_size)
{
    const int*   ids    = (const int*)  d_in[0];
    const int*   tags   = (const int*)  d_in[1];
    const float* embed  = (const float*)d_in[2];
    const float* e0_wih = (const float*)d_in[3];
    const float* e0_whh = (const float*)d_in[4];
    const float* e0_b   = (const float*)d_in[5];
    const float* e1_wih = (const float*)d_in[6];
    const float* e1_whh = (const float*)d_in[7];
    const float* e1_b   = (const float*)d_in[8];
    const float* dwih   = (const float*)d_in[9];
    const float* dwhh   = (const float*)d_in[10];
    const float* db     = (const float*)d_in[11];
    const float* ow     = (const float*)d_in[12];
    const float* obv    = (const float*)d_in[13];
    float* out = (float*)d_out;

    cudaFuncSetAttribute(k_encP, cudaFuncAttributeMaxDynamicSharedMemorySize, ENC_SMEM);
    cudaFuncSetAttribute(k_decP, cudaFuncAttributeMaxDynamicSharedMemorySize, DEC_SMEM);

    // 1. embedding
    k_embed<<<(LN_*E_/4 + 255)/256, 256>>>(ids, embed);

    // 2. enc0
    {
        dim3 gg(G4E_/128, LN_/128, 2);
        k_gemm_bias<<<gg, 256>>>(0, e0_wih, e0_b, E_);
    }
    k_encP<<<NB_, 256, ENC_SMEM>>>(0, e0_whh);

    // 3. enc1
    {
        dim3 gg(G4E_/128, LN_/128, 2);
        k_gemm_bias<<<gg, 256>>>(1, e1_wih, e1_b, 2*HE_);
    }
    k_encP<<<NB_, 256, ENC_SMEM>>>(1, e1_whh);

    // 4. decoder
    k_dec_init<<<(N_*HD_ + 255)/256, 256>>>();
    k_decP<<<NB_, 256, DEC_SMEM>>>(dwhh, dwih, db, ow, obv, tags, out);

    // 5. loss
    k_loss<<<1, 256>>>(out);
}

// round 9
// speedup vs baseline: 1.5507x; 1.0501x over previous
#include <cuda_runtime.h>

typedef unsigned long long ull;

#define N_ 128
#define L_ 160
#define E_ 512
#define HE_ 512
#define HD_ 1024
#define T_ 128
#define LN_ (L_*N_)
#define G4E_ 2048
#define NB_ 128u

#define K4E_ 128     // HE/4 per K-group
#define NCHE_ 16     // K4E/8 chunks
#define K4D_ 256     // HD/4
#define NCHD_ 32

// ---------------- scratch (device globals) ----------------
__device__ __align__(16) float g_xs[LN_*E_];
__device__ __align__(16) float g_G[2][(size_t)LN_*G4E_];
__device__ __align__(16) float g_h1[(size_t)LN_*2*HE_];
__device__ __align__(16) float g_enc[(size_t)LN_*2*HE_];
__device__ __align__(16) float g_eh[2][2][N_*HE_];   // [phase][dir]
__device__ __align__(16) float g_ec[2][N_*HE_];      // [dir]
__device__ __align__(16) float g_dh[2][N_*HD_];
__device__ __align__(16) float g_dc[N_*HD_];
__device__ int   g_amax[N_];
__device__ float g_lterm[L_*N_];

__device__ unsigned g_bcnt = 0;
__device__ volatile unsigned g_bgen = 0;

__device__ __forceinline__ void fma2(ull& d, ull a, ull b){
    asm("fma.rn.f32x2 %0, %1, %2, %0;" : "+l"(d) : "l"(a), "l"(b));
}
__device__ __forceinline__ ull dup2(float x){
    ull r; asm("mov.b64 %0, {%1, %1};" : "=l"(r) : "f"(x)); return r;
}
__device__ __forceinline__ float2 unpack2(ull v){
    float2 r; asm("mov.b64 {%0, %1}, %2;" : "=f"(r.x), "=f"(r.y) : "l"(v)); return r;
}
__device__ __forceinline__ float sigf(float x){ return 1.f/(1.f+expf(-x)); }

__device__ __forceinline__ void gridbar(){
    __syncthreads();
    if (threadIdx.x == 0) {
        unsigned g = g_bgen;
        __threadfence();
        if (atomicAdd(&g_bcnt, 1u) == NB_ - 1u) {
            atomicExch(&g_bcnt, 0u);
            __threadfence();
            g_bgen = g + 1u;
        } else {
            while (g_bgen == g) { }
        }
        __threadfence();
    }
    __syncthreads();
}

// ---------------- embedding ----------------
__global__ void k_embed(const int* __restrict__ ids, const float* __restrict__ embed)
{
    int i = blockIdx.x*blockDim.x + threadIdx.x;
    const int tot = LN_*E_/4;
    if (i >= tot) return;
    int e4 = i % (E_/4);
    int ln = i / (E_/4);
    int l = ln / N_, n = ln % N_;
    int id = ids[n*L_ + l];
    reinterpret_cast<float4*>(g_xs)[i] =
        reinterpret_cast<const float4*>(embed + (size_t)id*E_)[e4];
}

// ---------------- big input GEMM: raw A smem, 8x8 thread tile, row-pair f32x2 ----------------
__global__ __launch_bounds__(256) void k_gemm_bias(int asel, const float* __restrict__ Ball,
                                                   const float* __restrict__ biasall, int K)
{
    const float* A = asel ? g_h1 : g_xs;
    int z = blockIdx.z;
    const float* B = Ball + (size_t)z * G4E_ * K;
    const float* bias = biasall + z * G4E_;
    float* C = g_G[z];
    int m0 = blockIdx.y * 128, n0 = blockIdx.x * 128;
    __shared__ float As[8][132];
    __shared__ float Bs[8][132];
    int tid = threadIdx.x;
    int lr = tid >> 1, lk = (tid & 1) * 4;
    int ry = (tid >> 4) * 8;        // 8 consecutive rows
    int c4 = (tid & 15) * 4;        // cols c4..c4+3 and 64+c4..+3
    ull acc[4][8];                   // [row-pair][col: 0-3 -> c4+j, 4-7 -> 64+c4+j-4]
    #pragma unroll
    for (int p = 0; p < 4; p++)
        #pragma unroll
        for (int j = 0; j < 8; j++) acc[p][j] = 0ull;
    const float* Arow = A + (size_t)(m0+lr)*K + lk;
    const float* Brow = B + (size_t)(n0+lr)*K + lk;
    #pragma unroll 1
    for (int kc = 0; kc < K; kc += 8) {
        float4 av = *(const float4*)(Arow + kc);
        float4 bv = *(const float4*)(Brow + kc);
        __syncthreads();
        As[lk+0][lr]=av.x; As[lk+1][lr]=av.y; As[lk+2][lr]=av.z; As[lk+3][lr]=av.w;
        Bs[lk+0][lr]=bv.x; Bs[lk+1][lr]=bv.y; Bs[lk+2][lr]=bv.z; Bs[lk+3][lr]=bv.w;
        __syncthreads();
        #pragma unroll
        for (int kk = 0; kk < 8; kk++) {
            ulonglong2 aA = *(const ulonglong2*)&As[kk][ry];
            ulonglong2 aB = *(const ulonglong2*)&As[kk][ry+4];
            float4 b0 = *(const float4*)&Bs[kk][c4];
            float4 b1 = *(const float4*)&Bs[kk][64+c4];
            ull q[8] = {dup2(b0.x),dup2(b0.y),dup2(b0.z),dup2(b0.w),
                        dup2(b1.x),dup2(b1.y),dup2(b1.z),dup2(b1.w)};
            ull ar[4] = {aA.x, aA.y, aB.x, aB.y};
            #pragma unroll
            for (int p = 0; p < 4; p++)
                #pragma unroll
                for (int j = 0; j < 8; j++)
                    fma2(acc[p][j], ar[p], q[j]);
        }
    }
    float4 bia0 = *(const float4*)(bias + n0 + c4);
    float4 bia1 = *(const float4*)(bias + n0 + 64 + c4);
    #pragma unroll
    for (int p = 0; p < 4; p++) {
        float2 v[8];
        #pragma unroll
        for (int j = 0; j < 8; j++) v[j] = unpack2(acc[p][j]);
        float* C0 = C + (size_t)(m0+ry+2*p)*G4E_ + n0;
        float* C1 = C + (size_t)(m0+ry+2*p+1)*G4E_ + n0;
        *(float4*)(C0 + c4)    = make_float4(v[0].x+bia0.x, v[1].x+bia0.y, v[2].x+bia0.z, v[3].x+bia0.w);
        *(float4*)(C0 + 64+c4) = make_float4(v[4].x+bia1.x, v[5].x+bia1.y, v[6].x+bia1.z, v[7].x+bia1.w);
        *(float4*)(C1 + c4)    = make_float4(v[0].y+bia0.x, v[1].y+bia0.y, v[2].y+bia0.z, v[3].y+bia0.w);
        *(float4*)(C1 + 64+c4) = make_float4(v[4].y+bia1.x, v[5].y+bia1.y, v[6].y+bia1.z, v[7].y+bia1.w);
    }
}

// ================= persistent encoder: K-split-4, 8x8 thread tiles =================
// Block: 128 rows x 32 cols (c = gate*8+uu, u0=(b&63)*8). Whh resident in smem.
__global__ __launch_bounds__(256) void k_encP(int layer, const float* __restrict__ whh_all)
{
    extern __shared__ float sm[];
    float* Bs = sm;                        // [512][36]
    float* As = sm + 512*36;               // [2][32][132]
    float* gs = As + 2*32*132;             // [128][36]

    const int b  = blockIdx.x;
    const int d  = b >> 6;
    const int u0 = (b & 63) * 8;
    const int tid = threadIdx.x;
    // compute roles
    const int kg = tid >> 6;               // K-group 0..3
    const int slot = tid & 63;
    const int r0 = (slot >> 2) * 8;        // 8 rows
    const int c0 = (slot & 3) * 8;         // 8 cols
    // stage roles
    const int sr = tid & 127;              // sample row
    const int sh = tid >> 7;               // which pair of K-groups to stage

    // stage resident weights: Bs[k*36 + c], c = gate*8+uu -> wr = gate*HE + u0 + uu
    {
        const float* wb = whh_all + (size_t)d * (4*HE_) * HE_;
        for (int s = tid; s < 32*(HE_/4); s += 256) {
            int c = s / (HE_/4), k4 = s % (HE_/4);
            int wr = (c >> 3) * HE_ + u0 + (c & 7);
            float4 v = *(const float4*)(wb + (size_t)wr*HE_ + k4*4);
            Bs[(k4*4+0)*36 + c] = v.x;
            Bs[(k4*4+1)*36 + c] = v.y;
            Bs[(k4*4+2)*36 + c] = v.z;
            Bs[(k4*4+3)*36 + c] = v.w;
        }
    }
    float* obase = layer ? g_enc : g_h1;
    __syncthreads();

    for (int t = 0; t < L_; t++) {
        const int t_eff = d ? (L_-1-t) : t;
        ull acc[4][8];
        #pragma unroll
        for (int p = 0; p < 4; p++)
            #pragma unroll
            for (int j = 0; j < 8; j++) acc[p][j] = 0ull;

        if (t > 0) {
            const float* hin = g_eh[t & 1][d];
            const size_t sb = (size_t)sr*HE_;
            float ra[16];
            #pragma unroll
            for (int g = 0; g < 2; g++) {
                const float* p1 = hin + sb + (sh*2+g)*K4E_;
                float4 h0 = __ldcg((const float4*)p1);
                float4 h1 = __ldcg((const float4*)(p1+4));
                ra[g*8+0]=h0.x; ra[g*8+1]=h0.y; ra[g*8+2]=h0.z; ra[g*8+3]=h0.w;
                ra[g*8+4]=h1.x; ra[g*8+5]=h1.y; ra[g*8+6]=h1.z; ra[g*8+7]=h1.w;
            }
            #pragma unroll
            for (int g = 0; g < 2; g++) {
                float* q = As + ((sh*2+g)*8)*132 + sr;
                #pragma unroll
                for (int j = 0; j < 8; j++) q[j*132] = ra[g*8+j];
            }
            __syncthreads();
            int buf = 0;
            #pragma unroll 1
            for (int ch = 0; ch < NCHE_; ch++) {
                if (ch + 1 < NCHE_) {
                    #pragma unroll
                    for (int g = 0; g < 2; g++) {
                        const float* p1 = hin + sb + (sh*2+g)*K4E_ + (ch+1)*8;
                        float4 h0 = __ldcg((const float4*)p1);
                        float4 h1 = __ldcg((const float4*)(p1+4));
                        ra[g*8+0]=h0.x; ra[g*8+1]=h0.y; ra[g*8+2]=h0.z; ra[g*8+3]=h0.w;
                        ra[g*8+4]=h1.x; ra[g*8+5]=h1.y; ra[g*8+6]=h1.z; ra[g*8+7]=h1.w;
                    }
                }
                const float* ap = As + buf*4224 + (kg*8)*132 + r0;
                const float* bp = Bs + (kg*K4E_ + ch*8)*36 + c0;
                #pragma unroll
                for (int kk = 0; kk < 8; kk++) {
                    ulonglong2 aA = *(const ulonglong2*)(ap + kk*132);
                    ulonglong2 aB = *(const ulonglong2*)(ap + kk*132 + 4);
                    float4 b0 = *(const float4*)(bp + kk*36);
                    float4 b1 = *(const float4*)(bp + kk*36 + 4);
                    ull q[8] = {dup2(b0.x),dup2(b0.y),dup2(b0.z),dup2(b0.w),
                                dup2(b1.x),dup2(b1.y),dup2(b1.z),dup2(b1.w)};
                    ull ar[4] = {aA.x, aA.y, aB.x, aB.y};
                    #pragma unroll
                    for (int p = 0; p < 4; p++)
                        #pragma unroll
                        for (int j = 0; j < 8; j++)
                            fma2(acc[p][j], ar[p], q[j]);
                }
                if (ch + 1 < NCHE_) {
                    int nb = buf ^ 1;
                    #pragma unroll
                    for (int g = 0; g < 2; g++) {
                        float* q = As + nb*4224 + ((sh*2+g)*8)*132 + sr;
                        #pragma unroll
                        for (int j = 0; j < 8; j++) q[j*132] = ra[g*8+j];
                    }
                    __syncthreads();
                    buf = nb;
                }
            }
        }
        // reduce 4 K-group partials into gs (phase 0 writes, 1-3 add)
        #pragma unroll 1
        for (int ph2 = 0; ph2 < 4; ph2++) {
            if (kg == ph2) {
                #pragma unroll
                for (int p = 0; p < 4; p++) {
                    float2 v[8];
                    #pragma unroll
                    for (int j = 0; j < 8; j++) v[j] = unpack2(acc[p][j]);
                    float* w0 = gs + (r0+2*p)*36 + c0;
                    float* w1 = gs + (r0+2*p+1)*36 + c0;
                    float4 x0 = make_float4(v[0].x,v[1].x,v[2].x,v[3].x);
                    float4 x1 = make_float4(v[4].x,v[5].x,v[6].x,v[7].x);
                    float4 y0 = make_float4(v[0].y,v[1].y,v[2].y,v[3].y);
                    float4 y1 = make_float4(v[4].y,v[5].y,v[6].y,v[7].y);
                    if (ph2 == 0) {
                        *(float4*)w0 = x0; *(float4*)(w0+4) = x1;
                        *(float4*)w1 = y0; *(float4*)(w1+4) = y1;
                    } else {
                        float4 o0 = *(const float4*)w0, o1 = *(const float4*)(w0+4);
                        float4 o2 = *(const float4*)w1, o3 = *(const float4*)(w1+4);
                        *(float4*)w0 = make_float4(o0.x+x0.x,o0.y+x0.y,o0.z+x0.z,o0.w+x0.w);
                        *(float4*)(w0+4) = make_float4(o1.x+x1.x,o1.y+x1.y,o1.z+x1.z,o1.w+x1.w);
                        *(float4*)w1 = make_float4(o2.x+y0.x,o2.y+y0.y,o2.z+y0.z,o2.w+y0.w);
                        *(float4*)(w1+4) = make_float4(o3.x+y1.x,o3.y+y1.y,o3.z+y1.z,o3.w+y1.w);
                    }
                }
            }
            __syncthreads();
        }
        // epilogue
        {
            int row = tid >> 1;
            int uu0 = (tid & 1) * 4;
            int n = row;
            const float* Gp = g_G[d] + ((size_t)t_eff*N_ + n)*G4E_ + u0 + uu0;
            float4 Gi = *(const float4*)(Gp);
            float4 Gf = *(const float4*)(Gp + HE_);
            float4 Gc = *(const float4*)(Gp + 2*HE_);
            float4 Go = *(const float4*)(Gp + 3*HE_);
            float4 si = *(const float4*)&gs[row*36 + uu0];
            float4 sf = *(const float4*)&gs[row*36 + 8 + uu0];
            float4 sc = *(const float4*)&gs[row*36 + 16 + uu0];
            float4 so = *(const float4*)&gs[row*36 + 24 + uu0];
            float* cp = &g_ec[d][n*HE_ + u0 + uu0];
            float4 cv = (t > 0) ? *(const float4*)cp : make_float4(0.f,0.f,0.f,0.f);
            float4 cn, hn;
            cn.x = sigf(Gf.x+sf.x)*cv.x + sigf(Gi.x+si.x)*tanhf(Gc.x+sc.x);
            cn.y = sigf(Gf.y+sf.y)*cv.y + sigf(Gi.y+si.y)*tanhf(Gc.y+sc.y);
            cn.z = sigf(Gf.z+sf.z)*cv.z + sigf(Gi.z+si.z)*tanhf(Gc.z+sc.z);
            cn.w = sigf(Gf.w+sf.w)*cv.w + sigf(Gi.w+si.w)*tanhf(Gc.w+sc.w);
            hn.x = sigf(Go.x+so.x)*tanhf(cn.x);
            hn.y = sigf(Go.y+so.y)*tanhf(cn.y);
            hn.z = sigf(Go.z+so.z)*tanhf(cn.z);
            hn.w = sigf(Go.w+so.w)*tanhf(cn.w);
            *(float4*)cp = cn;
            *(float4*)&g_eh[1-(t&1)][d][n*HE_ + u0 + uu0] = hn;
            *(float4*)&obase[(size_t)t_eff*(N_*2*HE_) + (size_t)n*(2*HE_) + d*HE_ + u0 + uu0] = hn;
        }
        gridbar();
    }
}

// ---------------- decoder init ----------------
__global__ void k_dec_init()
{
    int i = blockIdx.x*blockDim.x + threadIdx.x;
    if (i < N_*HD_) {
        int n = i / HD_, k = i % HD_;
        g_dc[i] = g_enc[(size_t)n*(2*HE_) + HE_ + (k & (HE_-1))];
        g_dh[0][i] = 0.f;
    }
}

// ================= persistent decoder: K-split-4, 8x8 thread tiles =================
__global__ __launch_bounds__(256) void k_decP(const float* __restrict__ dwhh,
        const float* __restrict__ dwih, const float* __restrict__ db,
        const float* __restrict__ ow, const float* __restrict__ obv,
        const int* __restrict__ tags, float* __restrict__ out)
{
    extern __shared__ float sm[];
    float* Bs = sm;                        // [1024][36]
    float* As = sm + 1024*36;              // [2][32][132]
    float* gs = As + 2*32*132;             // [128][36]
    // logits overlay of As region:
    float* hs  = As;                       // [1024]
    float* red = As + 1024;                // [256]
    int*  redi = (int*)(red + 256);        // [128]

    const int b  = blockIdx.x;
    const int u0 = b * 8;
    const int tid = threadIdx.x;
    const int kg = tid >> 6;
    const int slot = tid & 63;
    const int r0 = (slot >> 2) * 8;
    const int c0 = (slot & 3) * 8;
    const int sr = tid & 127;
    const int sh = tid >> 7;

    for (int s = tid; s < 32*(HD_/4); s += 256) {
        int c = s / (HD_/4), k4 = s % (HD_/4);
        int wr = (c >> 3) * HD_ + u0 + (c & 7);
        float4 v = *(const float4*)(dwhh + (size_t)wr*HD_ + k4*4);
        Bs[(k4*4+0)*36 + c] = v.x;
        Bs[(k4*4+1)*36 + c] = v.y;
        Bs[(k4*4+2)*36 + c] = v.z;
        Bs[(k4*4+3)*36 + c] = v.w;
    }
    __syncthreads();

    for (int t = 0; t < L_; t++) {
        const int ph = t & 1;
        ull acc[4][8];
        #pragma unroll
        for (int p = 0; p < 4; p++)
            #pragma unroll
            for (int j = 0; j < 8; j++) acc[p][j] = 0ull;
        // ---- recurrent GEMM: A = h_prev + enc[t] ----
        {
            const float* hin  = g_dh[ph];
            const float* encT = g_enc + (size_t)t * (N_*HD_);
            const size_t sb = (size_t)sr*HD_;
            float ra[16];
            #pragma unroll
            for (int g = 0; g < 2; g++) {
                const float* p1 = hin + sb + (sh*2+g)*K4D_;
                const float* p2 = encT + sb + (sh*2+g)*K4D_;
                float4 h0 = __ldcg((const float4*)p1);
                float4 h1 = __ldcg((const float4*)(p1+4));
                float4 e0 = *(const float4*)p2;
                float4 e1 = *(const float4*)(p2+4);
                ra[g*8+0]=h0.x+e0.x; ra[g*8+1]=h0.y+e0.y; ra[g*8+2]=h0.z+e0.z; ra[g*8+3]=h0.w+e0.w;
                ra[g*8+4]=h1.x+e1.x; ra[g*8+5]=h1.y+e1.y; ra[g*8+6]=h1.z+e1.z; ra[g*8+7]=h1.w+e1.w;
            }
            #pragma unroll
            for (int g = 0; g < 2; g++) {
                float* q = As + ((sh*2+g)*8)*132 + sr;
                #pragma unroll
                for (int j = 0; j < 8; j++) q[j*132] = ra[g*8+j];
            }
            __syncthreads();
            int buf = 0;
            #pragma unroll 1
            for (int ch = 0; ch < NCHD_; ch++) {
                if (ch + 1 < NCHD_) {
                    #pragma unroll
                    for (int g = 0; g < 2; g++) {
                        const float* p1 = hin + sb + (sh*2+g)*K4D_ + (ch+1)*8;
                        const float* p2 = encT + sb + (sh*2+g)*K4D_ + (ch+1)*8;
                        float4 h0 = __ldcg((const float4*)p1);
                        float4 h1 = __ldcg((const float4*)(p1+4));
                        float4 e0 = *(const float4*)p2;
                        float4 e1 = *(const float4*)(p2+4);
                        ra[g*8+0]=h0.x+e0.x; ra[g*8+1]=h0.y+e0.y; ra[g*8+2]=h0.z+e0.z; ra[g*8+3]=h0.w+e0.w;
                        ra[g*8+4]=h1.x+e1.x; ra[g*8+5]=h1.y+e1.y; ra[g*8+6]=h1.z+e1.z; ra[g*8+7]=h1.w+e1.w;
                    }
                }
                const float* ap = As + buf*4224 + (kg*8)*132 + r0;
                const float* bp = Bs + (kg*K4D_ + ch*8)*36 + c0;
                #pragma unroll
                for (int kk = 0; kk < 8; kk++) {
                    ulonglong2 aA = *(const ulonglong2*)(ap + kk*132);
                    ulonglong2 aB = *(const ulonglong2*)(ap + kk*132 + 4);
                    float4 b0 = *(const float4*)(bp + kk*36);
                    float4 b1 = *(const float4*)(bp + kk*36 + 4);
                    ull q[8] = {dup2(b0.x),dup2(b0.y),dup2(b0.z),dup2(b0.w),
                                dup2(b1.x),dup2(b1.y),dup2(b1.z),dup2(b1.w)};
                    ull ar[4] = {aA.x, aA.y, aB.x, aB.y};
                    #pragma unroll
                    for (int p = 0; p < 4; p++)
                        #pragma unroll
                        for (int j = 0; j < 8; j++)
                            fma2(acc[p][j], ar[p], q[j]);
                }
                if (ch + 1 < NCHD_) {
                    int nb = buf ^ 1;
                    #pragma unroll
                    for (int g = 0; g < 2; g++) {
                        float* q = As + nb*4224 + ((sh*2+g)*8)*132 + sr;
                        #pragma unroll
                        for (int j = 0; j < 8; j++) q[j*132] = ra[g*8+j];
                    }
                    __syncthreads();
                    buf = nb;
                }
            }
        }
        // reduce partials
        #pragma unroll 1
        for (int ph2 = 0; ph2 < 4; ph2++) {
            if (kg == ph2) {
                #pragma unroll
                for (int p = 0; p < 4; p++) {
                    float2 v[8];
                    #pragma unroll
                    for (int j = 0; j < 8; j++) v[j] = unpack2(acc[p][j]);
                    float* w0 = gs + (r0+2*p)*36 + c0;
                    float* w1 = gs + (r0+2*p+1)*36 + c0;
                    float4 x0 = make_float4(v[0].x,v[1].x,v[2].x,v[3].x);
                    float4 x1 = make_float4(v[4].x,v[5].x,v[6].x,v[7].x);
                    float4 y0 = make_float4(v[0].y,v[1].y,v[2].y,v[3].y);
                    float4 y1 = make_float4(v[4].y,v[5].y,v[6].y,v[7].y);
                    if (ph2 == 0) {
                        *(float4*)w0 = x0; *(float4*)(w0+4) = x1;
                        *(float4*)w1 = y0; *(float4*)(w1+4) = y1;
                    } else {
                        float4 o0 = *(const float4*)w0, o1 = *(const float4*)(w0+4);
                        float4 o2 = *(const float4*)w1, o3 = *(const float4*)(w1+4);
                        *(float4*)w0 = make_float4(o0.x+x0.x,o0.y+x0.y,o0.z+x0.z,o0.w+x0.w);
                        *(float4*)(w0+4) = make_float4(o1.x+x1.x,o1.y+x1.y,o1.z+x1.z,o1.w+x1.w);
                        *(float4*)w1 = make_float4(o2.x+y0.x,o2.y+y0.y,o2.z+y0.z,o2.w+y0.w);
                        *(float4*)(w1+4) = make_float4(o3.x+y1.x,o3.y+y1.y,o3.z+y1.z,o3.w+y1.w);
                    }
                }
            }
            __syncthreads();
        }
        // ---- epilogue ----
        {
            int row = tid >> 1;
            int uu0 = (tid & 1) * 4;
            int n = row;
            int am = (t > 0) ? __ldcg(&g_amax[n]) : 0;
            float4 si = *(const float4*)&gs[row*36 + uu0];
            float4 sf = *(const float4*)&gs[row*36 + 8 + uu0];
            float4 sc = *(const float4*)&gs[row*36 + 16 + uu0];
            float4 so = *(const float4*)&gs[row*36 + 24 + uu0];
            float4 bi = *(const float4*)(db + u0 + uu0);
            float4 bf = *(const float4*)(db + HD_ + u0 + uu0);
            float4 bc = *(const float4*)(db + 2*HD_ + u0 + uu0);
            float4 bo = *(const float4*)(db + 3*HD_ + u0 + uu0);
            float wi[4][4];
            #pragma unroll
            for (int g = 0; g < 4; g++)
                #pragma unroll
                for (int e = 0; e < 4; e++)
                    wi[g][e] = (t > 0) ? __ldg(dwih + (size_t)(g*HD_ + u0 + uu0 + e)*T_ + am) : 0.f;
            float gi[4] = {si.x+bi.x+wi[0][0], si.y+bi.y+wi[0][1], si.z+bi.z+wi[0][2], si.w+bi.w+wi[0][3]};
            float gf[4] = {sf.x+bf.x+wi[1][0], sf.y+bf.y+wi[1][1], sf.z+bf.z+wi[1][2], sf.w+bf.w+wi[1][3]};
            float gc[4] = {sc.x+bc.x+wi[2][0], sc.y+bc.y+wi[2][1], sc.z+bc.z+wi[2][2], sc.w+bc.w+wi[2][3]};
            float go[4] = {so.x+bo.x+wi[3][0], so.y+bo.y+wi[3][1], so.z+bo.z+wi[3][2], so.w+bo.w+wi[3][3]};
            float* cp = &g_dc[n*HD_ + u0 + uu0];
            float4 cv = *(const float4*)cp;
            float4 cn, hn;
            cn.x = sigf(gf[0])*cv.x + sigf(gi[0])*tanhf(gc[0]);
            cn.y = sigf(gf[1])*cv.y + sigf(gi[1])*tanhf(gc[1]);
            cn.z = sigf(gf[2])*cv.z + sigf(gi[2])*tanhf(gc[2]);
            cn.w = sigf(gf[3])*cv.w + sigf(gi[3])*tanhf(gc[3]);
            hn.x = sigf(go[0])*tanhf(cn.x);
            hn.y = sigf(go[1])*tanhf(cn.y);
            hn.z = sigf(go[2])*tanhf(cn.z);
            hn.w = sigf(go[3])*tanhf(cn.w);
            *(float4*)cp = cn;
            *(float4*)&g_dh[1-ph][n*HD_ + u0 + uu0] = hn;
        }
        gridbar();
        // ---- logits / softmax / argmax: block b = sample n ----
        {
            const int n = b;
            const int j = tid & 127;
            const int half = tid >> 7;
            const float* hsrc = g_dh[1-ph] + (size_t)n*HD_;
            for (int k = tid; k < HD_; k += 256) hs[k] = __ldcg(hsrc + k);
            __syncthreads();
            ull s0 = 0ull, s1 = 0ull;
            const float* wrow = ow + (size_t)j*HD_ + half*512;
            const float* hh = hs + half*512;
            #pragma unroll 8
            for (int k = 0; k < 512; k += 8) {
                ulonglong2 w01 = *(const ulonglong2*)(wrow + k);
                ulonglong2 w23 = *(const ulonglong2*)(wrow + k + 4);
                ulonglong2 h01 = *(const ulonglong2*)(hh + k);
                ulonglong2 h23 = *(const ulonglong2*)(hh + k + 4);
                fma2(s0, w01.x, h01.x);
                fma2(s1, w01.y, h01.y);
                fma2(s0, w23.x, h23.x);
                fma2(s1, w23.y, h23.y);
            }
            float2 q0 = unpack2(s0), q1 = unpack2(s1);
            red[tid] = (q0.x + q0.y) + (q1.x + q1.y);
            __syncthreads();
            float accv = obv[j] + red[j] + red[j+128];
            __syncthreads();
            if (half == 0) red[j] = accv;
            __syncthreads();
            for (int s = 64; s > 0; s >>= 1) { if (tid < s) red[tid] = fmaxf(red[tid], red[tid+s]); __syncthreads(); }
            float mx = red[0]; __syncthreads();
            float ev = expf(accv - mx);
            if (half == 0) red[j] = ev;
            __syncthreads();
            for (int s = 64; s > 0; s >>= 1) { if (tid < s) red[tid] += red[tid+s]; __syncthreads(); }
            float sum = red[0];
            if (half == 0) out[((size_t)n*L_ + t)*T_ + j] = ev / sum;
            int tag = tags[n*L_ + t];
            if (tid == tag) g_lterm[t*N_ + n] = -(accv - mx - logf(sum)) / (float)N_;
            __syncthreads();
            if (half == 0) { red[j] = accv; redi[j] = j; }
            __syncthreads();
            for (int s = 64; s > 0; s >>= 1) {
                if (tid < s) {
                    float o = red[tid+s]; int oi = redi[tid+s];
                    if (o > red[tid] || (o == red[tid] && oi < redi[tid])) { red[tid] = o; redi[tid] = oi; }
                }
                __syncthreads();
            }
            if (tid == 0) g_amax[n] = redi[0];
        }
        gridbar();
    }
}

// ---------------- deterministic loss reduction ----------------
__global__ void k_loss(float* __restrict__ out)
{
    __shared__ float red[256];
    float s = 0.f;
    for (int i = threadIdx.x; i < L_*N_; i += 256) s += g_lterm[i];
    red[threadIdx.x] = s; __syncthreads();
    for (int st = 128; st > 0; st >>= 1) {
        if (threadIdx.x < st) red[threadIdx.x] += red[threadIdx.x + st];
        __syncthreads();
    }
    if (threadIdx.x == 0) out[(size_t)N_*L_*T_] = red[0];
}

// ---------------- launcher ----------------
#define ENC_SMEM ((512*36 + 2*32*132 + 128*36)*4)
#define DEC_SMEM ((1024*36 + 2*32*132 + 128*36)*4)

extern "C" void kernel_launch(void* const* d_in, const int* in_sizes, int n_in,
                              void* d_out, int out_size)
{
    const int*   ids    = (const int*)  d_in[0];
    const int*   tags   = (const int*)  d_in[1];
    const float* embed  = (const float*)d_in[2];
    const float* e0_wih = (const float*)d_in[3];
    const float* e0_whh = (const float*)d_in[4];
    const float* e0_b   = (const float*)d_in[5];
    const float* e1_wih = (const float*)d_in[6];
    const float* e1_whh = (const float*)d_in[7];
    const float* e1_b   = (const float*)d_in[8];
    const float* dwih   = (const float*)d_in[9];
    const float* dwhh   = (const float*)d_in[10];
    const float* db     = (const float*)d_in[11];
    const float* ow     = (const float*)d_in[12];
    const float* obv    = (const float*)d_in[13];
    float* out = (float*)d_out;

    cudaFuncSetAttribute(k_encP, cudaFuncAttributeMaxDynamicSharedMemorySize, ENC_SMEM);
    cudaFuncSetAttribute(k_decP, cudaFuncAttributeMaxDynamicSharedMemorySize, DEC_SMEM);

    // 1. embedding
    k_embed<<<(LN_*E_/4 + 255)/256, 256>>>(ids, embed);

    // 2. enc0
    {
        dim3 gg(G4E_/128, LN_/128, 2);
        k_gemm_bias<<<gg, 256>>>(0, e0_wih, e0_b, E_);
    }
    k_encP<<<NB_, 256, ENC_SMEM>>>(0, e0_whh);

    // 3. enc1
    {
        dim3 gg(G4E_/128, LN_/128, 2);
        k_gemm_bias<<<gg, 256>>>(1, e1_wih, e1_b, 2*HE_);
    }
    k_encP<<<NB_, 256, ENC_SMEM>>>(1, e1_whh);

    // 4. decoder
    k_dec_init<<<(N_*HD_ + 255)/256, 256>>>();
    k_decP<<<NB_, 256, DEC_SMEM>>>(dwhh, dwih, db, ow, obv, tags, out);

    // 5. loss
    k_loss<<<1, 256>>>(out);
}

// round 10
// speedup vs baseline: 1.7130x; 1.1047x over previous
#include <cuda_runtime.h>

typedef unsigned long long ull;

#define N_ 128
#define L_ 160
#define E_ 512
#define HE_ 512
#define HD_ 1024
#define T_ 128
#define LN_ (L_*N_)
#define G4E_ 2048
#define NB_ 128u

// ---------------- scratch (device globals) ----------------
__device__ __align__(16) float g_xs[LN_*E_];
__device__ __align__(16) float g_G[2][(size_t)LN_*G4E_];
__device__ __align__(16) float g_h1[(size_t)LN_*2*HE_];
__device__ __align__(16) float g_enc[(size_t)LN_*2*HE_];
__device__ __align__(16) float g_eh[2][2][N_*HE_];   // [phase][dir]
__device__ __align__(16) float g_ec[2][N_*HE_];      // [dir]
__device__ __align__(16) float g_dh[2][N_*HD_];
__device__ __align__(16) float g_dc[N_*HD_];
__device__ int   g_amax[N_];
__device__ float g_lterm[L_*N_];

__device__ unsigned g_bcnt = 0;
__device__ volatile unsigned g_bgen = 0;

__device__ __forceinline__ void fma2(ull& d, ull a, ull b){
    asm("fma.rn.f32x2 %0, %1, %2, %0;" : "+l"(d) : "l"(a), "l"(b));
}
__device__ __forceinline__ ull dup2(float x){
    ull r; asm("mov.b64 %0, {%1, %1};" : "=l"(r) : "f"(x)); return r;
}
__device__ __forceinline__ float2 unpack2(ull v){
    float2 r; asm("mov.b64 {%0, %1}, %2;" : "=f"(r.x), "=f"(r.y) : "l"(v)); return r;
}
__device__ __forceinline__ float sigf(float x){ return 1.f/(1.f+expf(-x)); }

__device__ __forceinline__ void gridbar(){
    __syncthreads();
    if (threadIdx.x == 0) {
        unsigned g = g_bgen;
        __threadfence();
        if (atomicAdd(&g_bcnt, 1u) == NB_ - 1u) {
            atomicExch(&g_bcnt, 0u);
            __threadfence();
            g_bgen = g + 1u;
        } else {
            while (g_bgen == g) { }
        }
        __threadfence();
    }
    __syncthreads();
}

// ---------------- embedding ----------------
__global__ void k_embed(const int* __restrict__ ids, const float* __restrict__ embed)
{
    int i = blockIdx.x*blockDim.x + threadIdx.x;
    const int tot = LN_*E_/4;
    if (i >= tot) return;
    int e4 = i % (E_/4);
    int ln = i / (E_/4);
    int l = ln / N_, n = ln % N_;
    int id = ids[n*L_ + l];
    reinterpret_cast<float4*>(g_xs)[i] =
        reinterpret_cast<const float4*>(embed + (size_t)id*E_)[e4];
}

// ---------------- big input GEMM (R9 version, fma 66%) ----------------
__global__ __launch_bounds__(256) void k_gemm_bias(int asel, const float* __restrict__ Ball,
                                                   const float* __restrict__ biasall, int K)
{
    const float* A = asel ? g_h1 : g_xs;
    int z = blockIdx.z;
    const float* B = Ball + (size_t)z * G4E_ * K;
    const float* bias = biasall + z * G4E_;
    float* C = g_G[z];
    int m0 = blockIdx.y * 128, n0 = blockIdx.x * 128;
    __shared__ float As[8][132];
    __shared__ float Bs[8][132];
    int tid = threadIdx.x;
    int lr = tid >> 1, lk = (tid & 1) * 4;
    int ry = (tid >> 4) * 8;
    int c4 = (tid & 15) * 4;
    ull acc[4][8];
    #pragma unroll
    for (int p = 0; p < 4; p++)
        #pragma unroll
        for (int j = 0; j < 8; j++) acc[p][j] = 0ull;
    const float* Arow = A + (size_t)(m0+lr)*K + lk;
    const float* Brow = B + (size_t)(n0+lr)*K + lk;
    #pragma unroll 1
    for (int kc = 0; kc < K; kc += 8) {
        float4 av = *(const float4*)(Arow + kc);
        float4 bv = *(const float4*)(Brow + kc);
        __syncthreads();
        As[lk+0][lr]=av.x; As[lk+1][lr]=av.y; As[lk+2][lr]=av.z; As[lk+3][lr]=av.w;
        Bs[lk+0][lr]=bv.x; Bs[lk+1][lr]=bv.y; Bs[lk+2][lr]=bv.z; Bs[lk+3][lr]=bv.w;
        __syncthreads();
        #pragma unroll
        for (int kk = 0; kk < 8; kk++) {
            ulonglong2 aA = *(const ulonglong2*)&As[kk][ry];
            ulonglong2 aB = *(const ulonglong2*)&As[kk][ry+4];
            float4 b0 = *(const float4*)&Bs[kk][c4];
            float4 b1 = *(const float4*)&Bs[kk][64+c4];
            ull q[8] = {dup2(b0.x),dup2(b0.y),dup2(b0.z),dup2(b0.w),
                        dup2(b1.x),dup2(b1.y),dup2(b1.z),dup2(b1.w)};
            ull ar[4] = {aA.x, aA.y, aB.x, aB.y};
            #pragma unroll
            for (int p = 0; p < 4; p++)
                #pragma unroll
                for (int j = 0; j < 8; j++)
                    fma2(acc[p][j], ar[p], q[j]);
        }
    }
    float4 bia0 = *(const float4*)(bias + n0 + c4);
    float4 bia1 = *(const float4*)(bias + n0 + 64 + c4);
    #pragma unroll
    for (int p = 0; p < 4; p++) {
        float2 v[8];
        #pragma unroll
        for (int j = 0; j < 8; j++) v[j] = unpack2(acc[p][j]);
        float* C0 = C + (size_t)(m0+ry+2*p)*G4E_ + n0;
        float* C1 = C + (size_t)(m0+ry+2*p+1)*G4E_ + n0;
        *(float4*)(C0 + c4)    = make_float4(v[0].x+bia0.x, v[1].x+bia0.y, v[2].x+bia0.z, v[3].x+bia0.w);
        *(float4*)(C0 + 64+c4) = make_float4(v[4].x+bia1.x, v[5].x+bia1.y, v[6].x+bia1.z, v[7].x+bia1.w);
        *(float4*)(C1 + c4)    = make_float4(v[0].y+bia0.x, v[1].y+bia0.y, v[2].y+bia0.z, v[3].y+bia0.w);
        *(float4*)(C1 + 64+c4) = make_float4(v[4].y+bia1.x, v[5].y+bia1.y, v[6].y+bia1.z, v[7].y+bia1.w);
    }
}

// ================= persistent encoder: 512 threads, K-split-8 =================
__global__ __launch_bounds__(512) void k_encP(int layer, const float* __restrict__ whh_all)
{
    extern __shared__ float sm[];
    float* Bs = sm;                        // [512][36]
    float* As = sm + 512*36;               // [2][32][132]
    float* gs = As + 2*32*132;             // [128][36]

    const int b  = blockIdx.x;
    const int d  = b >> 6;
    const int u0 = (b & 63) * 8;
    const int tid = threadIdx.x;
    const int kg = tid >> 6;               // K-group 0..7
    const int slot = tid & 63;
    const int r0 = (slot >> 2) * 8;
    const int c0 = (slot & 3) * 8;
    const int sr = tid & 127;              // stage row
    const int sg = tid >> 7;               // stage group 0..3 -> kg pair (2sg,2sg+1)

    {
        const float* wb = whh_all + (size_t)d * (4*HE_) * HE_;
        for (int s = tid; s < 32*(HE_/4); s += 512) {
            int c = s / (HE_/4), k4 = s % (HE_/4);
            int wr = (c >> 3) * HE_ + u0 + (c & 7);
            float4 v = *(const float4*)(wb + (size_t)wr*HE_ + k4*4);
            Bs[(k4*4+0)*36 + c] = v.x;
            Bs[(k4*4+1)*36 + c] = v.y;
            Bs[(k4*4+2)*36 + c] = v.z;
            Bs[(k4*4+3)*36 + c] = v.w;
        }
    }
    float* obase = layer ? g_enc : g_h1;
    __syncthreads();

    for (int t = 0; t < L_; t++) {
        const int t_eff = d ? (L_-1-t) : t;
        ull acc[4][8];
        #pragma unroll
        for (int p = 0; p < 4; p++)
            #pragma unroll
            for (int j = 0; j < 8; j++) acc[p][j] = 0ull;

        if (t > 0) {
            const float* hin = g_eh[t & 1][d];
            const size_t sb = (size_t)sr*HE_;
            float4 ra0 = __ldcg((const float4*)(hin + sb + (2*sg)*64));
            float4 ra1 = __ldcg((const float4*)(hin + sb + (2*sg+1)*64));
            {
                float* q0 = As + (8*sg)*132 + sr;
                float* q1 = As + (8*sg+4)*132 + sr;
                q0[0]=ra0.x; q0[132]=ra0.y; q0[264]=ra0.z; q0[396]=ra0.w;
                q1[0]=ra1.x; q1[132]=ra1.y; q1[264]=ra1.z; q1[396]=ra1.w;
            }
            __syncthreads();
            int buf = 0;
            #pragma unroll 1
            for (int ch = 0; ch < 16; ch++) {
                if (ch + 1 < 16) {
                    ra0 = __ldcg((const float4*)(hin + sb + (2*sg)*64 + (ch+1)*4));
                    ra1 = __ldcg((const float4*)(hin + sb + (2*sg+1)*64 + (ch+1)*4));
                }
                const float* ap = As + buf*4224 + (kg*4)*132 + r0;
                const float* bp = Bs + (kg*64 + ch*4)*36 + c0;
                #pragma unroll
                for (int kk = 0; kk < 4; kk++) {
                    ulonglong2 aA = *(const ulonglong2*)(ap + kk*132);
                    ulonglong2 aB = *(const ulonglong2*)(ap + kk*132 + 4);
                    float4 b0 = *(const float4*)(bp + kk*36);
                    float4 b1 = *(const float4*)(bp + kk*36 + 4);
                    ull q[8] = {dup2(b0.x),dup2(b0.y),dup2(b0.z),dup2(b0.w),
                                dup2(b1.x),dup2(b1.y),dup2(b1.z),dup2(b1.w)};
                    ull ar[4] = {aA.x, aA.y, aB.x, aB.y};
                    #pragma unroll
                    for (int p = 0; p < 4; p++)
                        #pragma unroll
                        for (int j = 0; j < 8; j++)
                            fma2(acc[p][j], ar[p], q[j]);
                }
                if (ch + 1 < 16) {
                    int nb = buf ^ 1;
                    float* q0 = As + nb*4224 + (8*sg)*132 + sr;
                    float* q1 = As + nb*4224 + (8*sg+4)*132 + sr;
                    q0[0]=ra0.x; q0[132]=ra0.y; q0[264]=ra0.z; q0[396]=ra0.w;
                    q1[0]=ra1.x; q1[132]=ra1.y; q1[264]=ra1.z; q1[396]=ra1.w;
                    __syncthreads();
                    buf = nb;
                }
            }
        }
        // reduce 8 K-group partials into gs
        #pragma unroll 1
        for (int ph2 = 0; ph2 < 8; ph2++) {
            if (kg == ph2) {
                #pragma unroll
                for (int p = 0; p < 4; p++) {
                    float2 v[8];
                    #pragma unroll
                    for (int j = 0; j < 8; j++) v[j] = unpack2(acc[p][j]);
                    float* w0 = gs + (r0+2*p)*36 + c0;
                    float* w1 = gs + (r0+2*p+1)*36 + c0;
                    float4 x0 = make_float4(v[0].x,v[1].x,v[2].x,v[3].x);
                    float4 x1 = make_float4(v[4].x,v[5].x,v[6].x,v[7].x);
                    float4 y0 = make_float4(v[0].y,v[1].y,v[2].y,v[3].y);
                    float4 y1 = make_float4(v[4].y,v[5].y,v[6].y,v[7].y);
                    if (ph2 == 0) {
                        *(float4*)w0 = x0; *(float4*)(w0+4) = x1;
                        *(float4*)w1 = y0; *(float4*)(w1+4) = y1;
                    } else {
                        float4 o0 = *(const float4*)w0, o1 = *(const float4*)(w0+4);
                        float4 o2 = *(const float4*)w1, o3 = *(const float4*)(w1+4);
                        *(float4*)w0 = make_float4(o0.x+x0.x,o0.y+x0.y,o0.z+x0.z,o0.w+x0.w);
                        *(float4*)(w0+4) = make_float4(o1.x+x1.x,o1.y+x1.y,o1.z+x1.z,o1.w+x1.w);
                        *(float4*)w1 = make_float4(o2.x+y0.x,o2.y+y0.y,o2.z+y0.z,o2.w+y0.w);
                        *(float4*)(w1+4) = make_float4(o3.x+y1.x,o3.y+y1.y,o3.z+y1.z,o3.w+y1.w);
                    }
                }
            }
            __syncthreads();
        }
        // epilogue (first 256 threads)
        if (tid < 256) {
            int row = tid >> 1;
            int uu0 = (tid & 1) * 4;
            int n = row;
            const float* Gp = g_G[d] + ((size_t)t_eff*N_ + n)*G4E_ + u0 + uu0;
            float4 Gi = *(const float4*)(Gp);
            float4 Gf = *(const float4*)(Gp + HE_);
            float4 Gc = *(const float4*)(Gp + 2*HE_);
            float4 Go = *(const float4*)(Gp + 3*HE_);
            float4 si = *(const float4*)&gs[row*36 + uu0];
            float4 sf = *(const float4*)&gs[row*36 + 8 + uu0];
            float4 sc = *(const float4*)&gs[row*36 + 16 + uu0];
            float4 so = *(const float4*)&gs[row*36 + 24 + uu0];
            float* cp = &g_ec[d][n*HE_ + u0 + uu0];
            float4 cv = (t > 0) ? *(const float4*)cp : make_float4(0.f,0.f,0.f,0.f);
            float4 cn, hn;
            cn.x = sigf(Gf.x+sf.x)*cv.x + sigf(Gi.x+si.x)*tanhf(Gc.x+sc.x);
            cn.y = sigf(Gf.y+sf.y)*cv.y + sigf(Gi.y+si.y)*tanhf(Gc.y+sc.y);
            cn.z = sigf(Gf.z+sf.z)*cv.z + sigf(Gi.z+si.z)*tanhf(Gc.z+sc.z);
            cn.w = sigf(Gf.w+sf.w)*cv.w + sigf(Gi.w+si.w)*tanhf(Gc.w+sc.w);
            hn.x = sigf(Go.x+so.x)*tanhf(cn.x);
            hn.y = sigf(Go.y+so.y)*tanhf(cn.y);
            hn.z = sigf(Go.z+so.z)*tanhf(cn.z);
            hn.w = sigf(Go.w+so.w)*tanhf(cn.w);
            *(float4*)cp = cn;
            *(float4*)&g_eh[1-(t&1)][d][n*HE_ + u0 + uu0] = hn;
            *(float4*)&obase[(size_t)t_eff*(N_*2*HE_) + (size_t)n*(2*HE_) + d*HE_ + u0 + uu0] = hn;
        }
        gridbar();
    }
}

// ---------------- decoder init ----------------
__global__ void k_dec_init()
{
    int i = blockIdx.x*blockDim.x + threadIdx.x;
    if (i < N_*HD_) {
        int n = i / HD_, k = i % HD_;
        g_dc[i] = g_enc[(size_t)n*(2*HE_) + HE_ + (k & (HE_-1))];
        g_dh[0][i] = 0.f;
    }
}

// ================= persistent decoder: 512 threads, K-split-8 =================
__global__ __launch_bounds__(512) void k_decP(const float* __restrict__ dwhh,
        const float* __restrict__ dwih, const float* __restrict__ db,
        const float* __restrict__ ow, const float* __restrict__ obv,
        const int* __restrict__ tags, float* __restrict__ out)
{
    extern __shared__ float sm[];
    float* Bs = sm;                        // [1024][36]
    float* As = sm + 1024*36;              // [2][32][132]
    float* gs = As + 2*32*132;             // [128][36]
    // logits overlay of As region:
    float* hsv = As;                       // [1024]
    float* lg  = As + 1024;                // [128]
    float* red = lg + 128;                 // [128]
    int*  redi = (int*)(red + 128);        // [128]

    const int b  = blockIdx.x;
    const int u0 = b * 8;
    const int tid = threadIdx.x;
    const int kg = tid >> 6;
    const int slot = tid & 63;
    const int r0 = (slot >> 2) * 8;
    const int c0 = (slot & 3) * 8;
    const int sr = tid & 127;
    const int sg = tid >> 7;

    for (int s = tid; s < 32*(HD_/4); s += 512) {
        int c = s / (HD_/4), k4 = s % (HD_/4);
        int wr = (c >> 3) * HD_ + u0 + (c & 7);
        float4 v = *(const float4*)(dwhh + (size_t)wr*HD_ + k4*4);
        Bs[(k4*4+0)*36 + c] = v.x;
        Bs[(k4*4+1)*36 + c] = v.y;
        Bs[(k4*4+2)*36 + c] = v.z;
        Bs[(k4*4+3)*36 + c] = v.w;
    }
    __syncthreads();

    for (int t = 0; t < L_; t++) {
        const int ph = t & 1;
        ull acc[4][8];
        #pragma unroll
        for (int p = 0; p < 4; p++)
            #pragma unroll
            for (int j = 0; j < 8; j++) acc[p][j] = 0ull;
        // ---- recurrent GEMM: A = h_prev + enc[t] ----
        {
            const float* hin  = g_dh[ph];
            const float* encT = g_enc + (size_t)t * (N_*HD_);
            const size_t sb = (size_t)sr*HD_;
            float4 h0 = __ldcg((const float4*)(hin + sb + (2*sg)*128));
            float4 h1 = __ldcg((const float4*)(hin + sb + (2*sg+1)*128));
            float4 e0 = *(const float4*)(encT + sb + (2*sg)*128);
            float4 e1 = *(const float4*)(encT + sb + (2*sg+1)*128);
            float4 ra0 = make_float4(h0.x+e0.x, h0.y+e0.y, h0.z+e0.z, h0.w+e0.w);
            float4 ra1 = make_float4(h1.x+e1.x, h1.y+e1.y, h1.z+e1.z, h1.w+e1.w);
            {
                float* q0 = As + (8*sg)*132 + sr;
                float* q1 = As + (8*sg+4)*132 + sr;
                q0[0]=ra0.x; q0[132]=ra0.y; q0[264]=ra0.z; q0[396]=ra0.w;
                q1[0]=ra1.x; q1[132]=ra1.y; q1[264]=ra1.z; q1[396]=ra1.w;
            }
            __syncthreads();
            int buf = 0;
            #pragma unroll 1
            for (int ch = 0; ch < 32; ch++) {
                if (ch + 1 < 32) {
                    h0 = __ldcg((const float4*)(hin + sb + (2*sg)*128 + (ch+1)*4));
                    h1 = __ldcg((const float4*)(hin + sb + (2*sg+1)*128 + (ch+1)*4));
                    e0 = *(const float4*)(encT + sb + (2*sg)*128 + (ch+1)*4);
                    e1 = *(const float4*)(encT + sb + (2*sg+1)*128 + (ch+1)*4);
                    ra0 = make_float4(h0.x+e0.x, h0.y+e0.y, h0.z+e0.z, h0.w+e0.w);
                    ra1 = make_float4(h1.x+e1.x, h1.y+e1.y, h1.z+e1.z, h1.w+e1.w);
                }
                const float* ap = As + buf*4224 + (kg*4)*132 + r0;
                const float* bp = Bs + (kg*128 + ch*4)*36 + c0;
                #pragma unroll
                for (int kk = 0; kk < 4; kk++) {
                    ulonglong2 aA = *(const ulonglong2*)(ap + kk*132);
                    ulonglong2 aB = *(const ulonglong2*)(ap + kk*132 + 4);
                    float4 b0 = *(const float4*)(bp + kk*36);
                    float4 b1 = *(const float4*)(bp + kk*36 + 4);
                    ull q[8] = {dup2(b0.x),dup2(b0.y),dup2(b0.z),dup2(b0.w),
                                dup2(b1.x),dup2(b1.y),dup2(b1.z),dup2(b1.w)};
                    ull ar[4] = {aA.x, aA.y, aB.x, aB.y};
                    #pragma unroll
                    for (int p = 0; p < 4; p++)
                        #pragma unroll
                        for (int j = 0; j < 8; j++)
                            fma2(acc[p][j], ar[p], q[j]);
                }
                if (ch + 1 < 32) {
                    int nb = buf ^ 1;
                    float* q0 = As + nb*4224 + (8*sg)*132 + sr;
                    float* q1 = As + nb*4224 + (8*sg+4)*132 + sr;
                    q0[0]=ra0.x; q0[132]=ra0.y; q0[264]=ra0.z; q0[396]=ra0.w;
                    q1[0]=ra1.x; q1[132]=ra1.y; q1[264]=ra1.z; q1[396]=ra1.w;
                    __syncthreads();
                    buf = nb;
                }
            }
        }
        // reduce partials
        #pragma unroll 1
        for (int ph2 = 0; ph2 < 8; ph2++) {
            if (kg == ph2) {
                #pragma unroll
                for (int p = 0; p < 4; p++) {
                    float2 v[8];
                    #pragma unroll
                    for (int j = 0; j < 8; j++) v[j] = unpack2(acc[p][j]);
                    float* w0 = gs + (r0+2*p)*36 + c0;
                    float* w1 = gs + (r0+2*p+1)*36 + c0;
                    float4 x0 = make_float4(v[0].x,v[1].x,v[2].x,v[3].x);
                    float4 x1 = make_float4(v[4].x,v[5].x,v[6].x,v[7].x);
                    float4 y0 = make_float4(v[0].y,v[1].y,v[2].y,v[3].y);
                    float4 y1 = make_float4(v[4].y,v[5].y,v[6].y,v[7].y);
                    if (ph2 == 0) {
                        *(float4*)w0 = x0; *(float4*)(w0+4) = x1;
                        *(float4*)w1 = y0; *(float4*)(w1+4) = y1;
                    } else {
                        float4 o0 = *(const float4*)w0, o1 = *(const float4*)(w0+4);
                        float4 o2 = *(const float4*)w1, o3 = *(const float4*)(w1+4);
                        *(float4*)w0 = make_float4(o0.x+x0.x,o0.y+x0.y,o0.z+x0.z,o0.w+x0.w);
                        *(float4*)(w0+4) = make_float4(o1.x+x1.x,o1.y+x1.y,o1.z+x1.z,o1.w+x1.w);
                        *(float4*)w1 = make_float4(o2.x+y0.x,o2.y+y0.y,o2.z+y0.z,o2.w+y0.w);
                        *(float4*)(w1+4) = make_float4(o3.x+y1.x,o3.y+y1.y,o3.z+y1.z,o3.w+y1.w);
                    }
                }
            }
            __syncthreads();
        }
        // ---- epilogue (first 256 threads) ----
        if (tid < 256) {
            int row = tid >> 1;
            int uu0 = (tid & 1) * 4;
            int n = row;
            int am = (t > 0) ? __ldcg(&g_amax[n]) : 0;
            float4 si = *(const float4*)&gs[row*36 + uu0];
            float4 sf = *(const float4*)&gs[row*36 + 8 + uu0];
            float4 sc = *(const float4*)&gs[row*36 + 16 + uu0];
            float4 so = *(const float4*)&gs[row*36 + 24 + uu0];
            float4 bi = *(const float4*)(db + u0 + uu0);
            float4 bf = *(const float4*)(db + HD_ + u0 + uu0);
            float4 bc = *(const float4*)(db + 2*HD_ + u0 + uu0);
            float4 bo = *(const float4*)(db + 3*HD_ + u0 + uu0);
            float wi[4][4];
            #pragma unroll
            for (int g = 0; g < 4; g++)
                #pragma unroll
                for (int e = 0; e < 4; e++)
                    wi[g][e] = (t > 0) ? __ldg(dwih + (size_t)(g*HD_ + u0 + uu0 + e)*T_ + am) : 0.f;
            float gi[4] = {si.x+bi.x+wi[0][0], si.y+bi.y+wi[0][1], si.z+bi.z+wi[0][2], si.w+bi.w+wi[0][3]};
            float gf[4] = {sf.x+bf.x+wi[1][0], sf.y+bf.y+wi[1][1], sf.z+bf.z+wi[1][2], sf.w+bf.w+wi[1][3]};
            float gc[4] = {sc.x+bc.x+wi[2][0], sc.y+bc.y+wi[2][1], sc.z+bc.z+wi[2][2], sc.w+bc.w+wi[2][3]};
            float go[4] = {so.x+bo.x+wi[3][0], so.y+bo.y+wi[3][1], so.z+bo.z+wi[3][2], so.w+bo.w+wi[3][3]};
            float* cp = &g_dc[n*HD_ + u0 + uu0];
            float4 cv = *(const float4*)cp;
            float4 cn, hn;
            cn.x = sigf(gf[0])*cv.x + sigf(gi[0])*tanhf(gc[0]);
            cn.y = sigf(gf[1])*cv.y + sigf(gi[1])*tanhf(gc[1]);
            cn.z = sigf(gf[2])*cv.z + sigf(gi[2])*tanhf(gc[2]);
            cn.w = sigf(gf[3])*cv.w + sigf(gi[3])*tanhf(gc[3]);
            hn.x = sigf(go[0])*tanhf(cn.x);
            hn.y = sigf(go[1])*tanhf(cn.y);
            hn.z = sigf(go[2])*tanhf(cn.z);
            hn.w = sigf(go[3])*tanhf(cn.w);
            *(float4*)cp = cn;
            *(float4*)&g_dh[1-ph][n*HD_ + u0 + uu0] = hn;
        }
        gridbar();
        // ---- logits / softmax / argmax: block b = sample n, coalesced rows ----
        {
            const int n = b;
            const float* hsrc = g_dh[1-ph] + (size_t)n*HD_;
            for (int k = tid; k < HD_; k += 512) hsv[k] = __ldcg(hsrc + k);
            __syncthreads();
            {
                int w = tid >> 5, lane = tid & 31;
                #pragma unroll 1
                for (int rr = 0; rr < 8; rr++) {
                    int j = w*8 + rr;
                    const float* wrow = ow + (size_t)j*HD_ + lane*4;
                    const float* hh = hsv + lane*4;
                    ull s0 = 0ull, s1 = 0ull;
                    #pragma unroll
                    for (int i = 0; i < 8; i++) {
                        ulonglong2 wp = *(const ulonglong2*)(wrow + i*128);
                        ulonglong2 hp = *(const ulonglong2*)(hh + i*128);
                        fma2(s0, wp.x, hp.x);
                        fma2(s1, wp.y, hp.y);
                    }
                    float2 q0 = unpack2(s0), q1 = unpack2(s1);
                    float p = (q0.x + q0.y) + (q1.x + q1.y);
                    #pragma unroll
                    for (int off = 16; off > 0; off >>= 1)
                        p += __shfl_down_sync(0xffffffffu, p, off);
                    if (lane == 0) lg[j] = p + obv[j];
                }
            }
            __syncthreads();
            if (tid < 128) red[tid] = lg[tid];
            __syncthreads();
            for (int s = 64; s > 0; s >>= 1) { if (tid < s) red[tid] = fmaxf(red[tid], red[tid+s]); __syncthreads(); }
            float mx = red[0]; __syncthreads();
            float accv = 0.f, ev = 0.f;
            if (tid < 128) { accv = lg[tid]; ev = expf(accv - mx); red[tid] = ev; }
            __syncthreads();
            for (int s = 64; s > 0; s >>= 1) { if (tid < s) red[tid] += red[tid+s]; __syncthreads(); }
            float sum = red[0];
            if (tid < 128) out[((size_t)n*L_ + t)*T_ + tid] = ev / sum;
            int tag = tags[n*L_ + t];
            if (tid == tag) g_lterm[t*N_ + n] = -(accv - mx - logf(sum)) / (float)N_;
            __syncthreads();
            if (tid < 128) { red[tid] = lg[tid]; redi[tid] = tid; }
            __syncthreads();
            for (int s = 64; s > 0; s >>= 1) {
                if (tid < s) {
                    float o = red[tid+s]; int oi = redi[tid+s];
                    if (o > red[tid] || (o == red[tid] && oi < redi[tid])) { red[tid] = o; redi[tid] = oi; }
                }
                __syncthreads();
            }
            if (tid == 0) g_amax[n] = redi[0];
        }
        gridbar();
    }
}

// ---------------- deterministic loss reduction ----------------
__global__ void k_loss(float* __restrict__ out)
{
    __shared__ float red[256];
    float s = 0.f;
    for (int i = threadIdx.x; i < L_*N_; i += 256) s += g_lterm[i];
    red[threadIdx.x] = s; __syncthreads();
    for (int st = 128; st > 0; st >>= 1) {
        if (threadIdx.x < st) red[threadIdx.x] += red[threadIdx.x + st];
        __syncthreads();
    }
    if (threadIdx.x == 0) out[(size_t)N_*L_*T_] = red[0];
}

// ---------------- launcher ----------------
#define ENC_SMEM ((512*36 + 2*32*132 + 128*36)*4)
#define DEC_SMEM ((1024*36 + 2*32*132 + 128*36)*4)

extern "C" void kernel_launch(void* const* d_in, const int* in_sizes, int n_in,
                              void* d_out, int out_size)
{
    const int*   ids    = (const int*)  d_in[0];
    const int*   tags   = (const int*)  d_in[1];
    const float* embed  = (const float*)d_in[2];
    const float* e0_wih = (const float*)d_in[3];
    const float* e0_whh = (const float*)d_in[4];
    const float* e0_b   = (const float*)d_in[5];
    const float* e1_wih = (const float*)d_in[6];
    const float* e1_whh = (const float*)d_in[7];
    const float* e1_b   = (const float*)d_in[8];
    const float* dwih   = (const float*)d_in[9];
    const float* dwhh   = (const float*)d_in[10];
    const float* db     = (const float*)d_in[11];
    const float* ow     = (const float*)d_in[12];
    const float* obv    = (const float*)d_in[13];
    float* out = (float*)d_out;

    cudaFuncSetAttribute(k_encP, cudaFuncAttributeMaxDynamicSharedMemorySize, ENC_SMEM);
    cudaFuncSetAttribute(k_decP, cudaFuncAttributeMaxDynamicSharedMemorySize, DEC_SMEM);

    // 1. embedding
    k_embed<<<(LN_*E_/4 + 255)/256, 256>>>(ids, embed);

    // 2. enc0
    {
        dim3 gg(G4E_/128, LN_/128, 2);
        k_gemm_bias<<<gg, 256>>>(0, e0_wih, e0_b, E_);
    }
    k_encP<<<NB_, 512, ENC_SMEM>>>(0, e0_whh);

    // 3. enc1
    {
        dim3 gg(G4E_/128, LN_/128, 2);
        k_gemm_bias<<<gg, 256>>>(1, e1_wih, e1_b, 2*HE_);
    }
    k_encP<<<NB_, 512, ENC_SMEM>>>(1, e1_whh);

    // 4. decoder
    k_dec_init<<<(N_*HD_ + 255)/256, 256>>>();
    k_decP<<<NB_, 512, DEC_SMEM>>>(dwhh, dwih, db, ow, obv, tags, out);

    // 5. loss
    k_loss<<<1, 256>>>(out);
}